// round 5
// baseline (speedup 1.0000x reference)
#include <cuda_runtime.h>
#include <cuda_bf16.h>
#include <math.h>

#define BDIM 4096
#define SEQ  2048
#define NB   2
#define MTOK 4096

typedef unsigned int u32;

// ---------------------------------------------------------------------------
// Static scratch
// ---------------------------------------------------------------------------
__device__ float g_xA[(size_t)NB * SEQ * BDIM];    // fp32 xA (needs transpose)
__device__ float g_sc[(size_t)NB * BDIM * BDIM];   // fp32 scores

static const size_t PLANE_X  = (size_t)MTOK * BDIM;
static const size_t PLANE_W  = (size_t)BDIM * BDIM;
static const size_t PLANE_AT = (size_t)NB * BDIM * SEQ;
static const size_t PLANE_SC = (size_t)NB * BDIM * BDIM;

__device__ __nv_bfloat16 s_x  [2 * PLANE_X];   // x split
__device__ __nv_bfloat16 s_w1 [2 * PLANE_W];   // W1 split (natural [N,K])
__device__ __nv_bfloat16 s_w2 [2 * PLANE_W];
__device__ __nv_bfloat16 s_w4 [2 * PLANE_W];
__device__ __nv_bfloat16 s_wo [2 * PLANE_W];
__device__ __nv_bfloat16 s_xAT[2 * PLANE_AT];  // xA^T split [b][D][S]
__device__ __nv_bfloat16 s_xB [2 * PLANE_X];   // xB split [b][S][D]
__device__ __nv_bfloat16 s_at [2 * PLANE_SC];  // attn split [b][D][D]
__device__ __nv_bfloat16 s_xO [2 * PLANE_X];
__device__ __nv_bfloat16 s_t  [2 * PLANE_X];

// ---------------------------------------------------------------------------
// helpers
// ---------------------------------------------------------------------------
__device__ __forceinline__ void split2(float v, __nv_bfloat16& h, __nv_bfloat16& l) {
    h = __float2bfloat16(v);
    l = __float2bfloat16(v - __bfloat162float(h));
}
__device__ __forceinline__ void cpa16(u32 dst, const void* src) {
    asm volatile("cp.async.cg.shared.global [%0], [%1], 16;\n" :: "r"(dst), "l"(src));
}
__device__ __forceinline__ void cp_commit() { asm volatile("cp.async.commit_group;\n"); }

__device__ __forceinline__ void ldsm_x4(u32* r, u32 addr) {
    asm volatile("ldmatrix.sync.aligned.m8n8.x4.shared.b16 {%0,%1,%2,%3}, [%4];\n"
                 : "=r"(r[0]), "=r"(r[1]), "=r"(r[2]), "=r"(r[3]) : "r"(addr));
}
__device__ __forceinline__ void ldsm_x4t(u32* r, u32 addr) {
    asm volatile("ldmatrix.sync.aligned.m8n8.x4.trans.shared.b16 {%0,%1,%2,%3}, [%4];\n"
                 : "=r"(r[0]), "=r"(r[1]), "=r"(r[2]), "=r"(r[3]) : "r"(addr));
}
__device__ __forceinline__ void mma16816(float* d, const u32* a, const u32* b) {
    asm volatile("mma.sync.aligned.m16n8k16.row.col.f32.bf16.bf16.f32 "
                 "{%0,%1,%2,%3}, {%4,%5,%6,%7}, {%8,%9}, {%0,%1,%2,%3};\n"
                 : "+f"(d[0]), "+f"(d[1]), "+f"(d[2]), "+f"(d[3])
                 : "r"(a[0]), "r"(a[1]), "r"(a[2]), "r"(a[3]), "r"(b[0]), "r"(b[1]));
}

// ---------------------------------------------------------------------------
// split kernels
// ---------------------------------------------------------------------------
__global__ void split_rm(const float* __restrict__ in,
                         __nv_bfloat16* __restrict__ hi,
                         __nv_bfloat16* __restrict__ lo, size_t n4)
{
    size_t i = (size_t)blockIdx.x * blockDim.x + threadIdx.x;
    if (i >= n4) return;
    float4 v = reinterpret_cast<const float4*>(in)[i];
    __nv_bfloat16 h0,l0,h1,l1,h2,l2,h3,l3;
    split2(v.x,h0,l0); split2(v.y,h1,l1); split2(v.z,h2,l2); split2(v.w,h3,l3);
    reinterpret_cast<__nv_bfloat162*>(hi)[2*i+0] = __halves2bfloat162(h0,h1);
    reinterpret_cast<__nv_bfloat162*>(hi)[2*i+1] = __halves2bfloat162(h2,h3);
    reinterpret_cast<__nv_bfloat162*>(lo)[2*i+0] = __halves2bfloat162(l0,l1);
    reinterpret_cast<__nv_bfloat162*>(lo)[2*i+1] = __halves2bfloat162(l2,l3);
}

// in: [R,C] fp32 -> out hi/lo: [C,R] bf16   (batched via blockIdx.z)
__global__ void split_tr(const float* __restrict__ in,
                         __nv_bfloat16* __restrict__ hi,
                         __nv_bfloat16* __restrict__ lo, int R, int C)
{
    __shared__ float tile[32][33];
    size_t boff = (size_t)blockIdx.z * R * C;
    const float* inb = in + boff;
    __nv_bfloat16* hib = hi + boff;
    __nv_bfloat16* lob = lo + boff;
    int c0 = blockIdx.x * 32, r0 = blockIdx.y * 32;
    int tx = threadIdx.x;
#pragma unroll
    for (int i = threadIdx.y; i < 32; i += 8)
        tile[i][tx] = inb[(size_t)(r0 + i) * C + c0 + tx];
    __syncthreads();
#pragma unroll
    for (int i = threadIdx.y; i < 32; i += 8) {
        float v = tile[tx][i];
        __nv_bfloat16 h, l; split2(v, h, l);
        size_t o = (size_t)(c0 + i) * R + r0 + tx;
        hib[o] = h; lob[o] = l;
    }
}

// softmax rows of 4096, fp32 in -> split bf16 out
__global__ __launch_bounds__(256)
void softmax_split(const float* __restrict__ sc,
                   __nv_bfloat16* __restrict__ ah,
                   __nv_bfloat16* __restrict__ al)
{
    __shared__ float sred[32];
    size_t roff = (size_t)blockIdx.x * BDIM;
    const float* p = sc + roff;
    const int tid = threadIdx.x;

    float v[16];
    float m = -3.0e38f;
#pragma unroll
    for (int i = 0; i < 16; i++) { v[i] = p[tid + 256 * i]; m = fmaxf(m, v[i]); }
#pragma unroll
    for (int o = 16; o > 0; o >>= 1) m = fmaxf(m, __shfl_xor_sync(0xffffffffu, m, o));
    if ((tid & 31) == 0) sred[tid >> 5] = m;
    __syncthreads();
    if (tid < 32) {
        float t = (tid < 8) ? sred[tid] : -3.0e38f;
#pragma unroll
        for (int o = 4; o > 0; o >>= 1) t = fmaxf(t, __shfl_xor_sync(0xffffffffu, t, o));
        if (tid == 0) sred[0] = t;
    }
    __syncthreads();
    m = sred[0];

    float s = 0.f;
#pragma unroll
    for (int i = 0; i < 16; i++) { v[i] = expf(v[i] - m); s += v[i]; }
#pragma unroll
    for (int o = 16; o > 0; o >>= 1) s += __shfl_xor_sync(0xffffffffu, s, o);
    __syncthreads();
    if ((tid & 31) == 0) sred[tid >> 5] = s;
    __syncthreads();
    if (tid < 32) {
        float t = (tid < 8) ? sred[tid] : 0.f;
#pragma unroll
        for (int o = 4; o > 0; o >>= 1) t += __shfl_xor_sync(0xffffffffu, t, o);
        if (tid == 0) sred[0] = t;
    }
    __syncthreads();
    float inv = 1.0f / sred[0];
#pragma unroll
    for (int i = 0; i < 16; i++) {
        float w = v[i] * inv;
        __nv_bfloat16 h, l; split2(w, h, l);
        ah[roff + tid + 256 * i] = h;
        al[roff + tid + 256 * i] = l;
    }
}

// ---------------------------------------------------------------------------
// Split-bf16 tensor-core GEMM v3.
//   A: [M,K] row-major split.
//   BT=true : B is [N,K] row-major (weights)        -> non-trans ldmatrix
//   BT=false: B is [K,N] row-major (activations)    -> trans ldmatrix
//   acc = Ah*Bh + Ah*Bl + Al*Bh, TERM-MAJOR inner loop (acc RAW distance 32).
// CTA 128x256, warp 64x64, 8 warps, BK=32, 3-stage cp.async pipeline.
// EPI: 0 fp32 | 1 fp32+bias | 2 split | 3 split(resid + silu(acc+bias))
// ---------------------------------------------------------------------------
#define A_PITCH 40
#define A_BUF   (128 * A_PITCH * 2)              // 10240 B per plane

template<int EPI, bool BT>
__global__ __launch_bounds__(256, 1)
void bgemm(const __nv_bfloat16* __restrict__ Ah, const __nv_bfloat16* __restrict__ Al,
           const __nv_bfloat16* __restrict__ Bh, const __nv_bfloat16* __restrict__ Bl,
           int K, int N,
           long sA, long sB, long sC,
           float* __restrict__ Cf,
           __nv_bfloat16* __restrict__ Ch, __nv_bfloat16* __restrict__ Cl,
           const float* __restrict__ bias, const float* __restrict__ resid)
{
    constexpr int B_PITCH = BT ? 40 : 264;
    constexpr int B_BUF   = BT ? (256 * 40 * 2) : (32 * 264 * 2);
    constexpr int SOFF_AL = A_BUF;
    constexpr int SOFF_BH = 2 * A_BUF;
    constexpr int SOFF_BL = 2 * A_BUF + B_BUF;
    constexpr int STAGE_BYTES = 2 * A_BUF + 2 * B_BUF;

    extern __shared__ __align__(16) char smem[];
    const u32 sbase = (u32)__cvta_generic_to_shared(smem);

    const int bz = blockIdx.z;
    Ah += (size_t)bz * sA; Al += (size_t)bz * sA;
    Bh += (size_t)bz * sB; Bl += (size_t)bz * sB;
    if (EPI == 0 || EPI == 1) Cf += (size_t)bz * sC;
    else { Ch += (size_t)bz * sC; Cl += (size_t)bz * sC; }

    // CTA swizzle (GROUP_M = 8)
    const int tiles_n = gridDim.x, tiles_m = gridDim.y;
    int bid = blockIdx.x + blockIdx.y * tiles_n;
    const int G = 8;
    int gsz = G * tiles_n;
    int g   = bid / gsz;
    int rem = bid - g * gsz;
    int gm  = min(G, tiles_m - g * G);
    const int m0 = (g * G + rem % gm) * 128;
    const int n0 = (rem / gm) * 256;

    const int tid  = threadIdx.x;
    const int lane = tid & 31;
    const int wid  = tid >> 5;
    const int wm   = (wid & 1) * 64;
    const int wn   = (wid >> 1) * 64;

    float acc[4][8][4];
#pragma unroll
    for (int i = 0; i < 4; i++)
#pragma unroll
        for (int j = 0; j < 8; j++)
#pragma unroll
            for (int q = 0; q < 4; q++) acc[i][j][q] = 0.f;

    // A staging decomposition (128 rows x 32k : 512 chunks of 16B per plane)
    const int a_row0 = tid >> 2,          a_kc0 = (tid & 3) << 3;
    const int a_row1 = (tid + 256) >> 2,  a_kc1 = ((tid + 256) & 3) << 3;

    const int nk = K >> 5;

#define STAGE(buf, k0) do {                                                          \
    u32 sb_ = sbase + (u32)(buf) * STAGE_BYTES;                                      \
    {                                                                                \
        u32 d0 = sb_ + (u32)(a_row0 * A_PITCH + a_kc0) * 2;                          \
        u32 d1 = sb_ + (u32)(a_row1 * A_PITCH + a_kc1) * 2;                          \
        const __nv_bfloat16* g0 = Ah + (size_t)(m0 + a_row0) * K + (k0) + a_kc0;     \
        const __nv_bfloat16* g1 = Ah + (size_t)(m0 + a_row1) * K + (k0) + a_kc1;     \
        cpa16(d0, g0); cpa16(d1, g1);                                                \
        cpa16(d0 + SOFF_AL, Al + (g0 - Ah));                                         \
        cpa16(d1 + SOFF_AL, Al + (g1 - Ah));                                         \
    }                                                                                \
    if (BT) {                                                                        \
        _Pragma("unroll")                                                            \
        for (int r_ = 0; r_ < 4; r_++) {                                             \
            int c_ = tid + (r_ << 8);                                                \
            int br_ = c_ >> 2, bk_ = (c_ & 3) << 3;                                  \
            u32 d_ = sb_ + SOFF_BH + (u32)(br_ * B_PITCH + bk_) * 2;                 \
            const __nv_bfloat16* gb_ = Bh + (size_t)(n0 + br_) * K + (k0) + bk_;     \
            cpa16(d_, gb_);                                                          \
            cpa16(d_ + B_BUF, Bl + (gb_ - Bh));                                      \
        }                                                                            \
    } else {                                                                         \
        _Pragma("unroll")                                                            \
        for (int r_ = 0; r_ < 4; r_++) {                                             \
            int c_ = tid + (r_ << 8);                                                \
            int br_ = c_ >> 5, bn_ = (c_ & 31) << 3;                                 \
            u32 d_ = sb_ + SOFF_BH + (u32)(br_ * B_PITCH + bn_) * 2;                 \
            const __nv_bfloat16* gb_ = Bh + (size_t)((k0) + br_) * N + n0 + bn_;     \
            cpa16(d_, gb_);                                                          \
            cpa16(d_ + B_BUF, Bl + (gb_ - Bh));                                      \
        }                                                                            \
    }                                                                                \
} while (0)

    STAGE(0, 0);
    cp_commit();
    STAGE(1, 32);
    cp_commit();

    // ldmatrix lane selectors
    const int aRowSel = lane & 15;              // A (non-trans)
    const int aColSel = (lane >> 4) << 3;
    const int tRowSel = (lane & 7) + (lane & 8);   // B trans path
    const int tColSel = (lane & 16) >> 1;
    const int wRowSel = ((lane >> 4) << 3) + (lane & 7);  // B non-trans (weights): n row
    const int wColSel = lane & 8;                          // k offset 0/8

    for (int kt = 0; kt < nk; kt++) {
        asm volatile("cp.async.wait_group 1;");
        __syncthreads();

        if (kt + 2 < nk) STAGE((kt + 2) % 3, (kt + 2) << 5);
        cp_commit();

        const u32 ab = sbase + (u32)(kt % 3) * STAGE_BYTES;
        const u32 bb = ab + SOFF_BH;

#pragma unroll
        for (int kk = 0; kk < 32; kk += 16) {
            u32 ah[4][4], al[4][4], bh[4][4], bl[4][4];
#pragma unroll
            for (int i = 0; i < 4; i++) {
                u32 off = (u32)((wm + i * 16 + aRowSel) * A_PITCH + kk + aColSel) * 2;
                ldsm_x4(ah[i], ab + off);
                ldsm_x4(al[i], ab + SOFF_AL + off);
            }
#pragma unroll
            for (int j2 = 0; j2 < 4; j2++) {
                if (BT) {
                    u32 off = (u32)((wn + j2 * 16 + wRowSel) * B_PITCH + kk + wColSel) * 2;
                    ldsm_x4(bh[j2], bb + off);
                    ldsm_x4(bl[j2], bb + B_BUF + off);
                } else {
                    u32 off = (u32)((kk + tRowSel) * B_PITCH + wn + j2 * 16 + tColSel) * 2;
                    ldsm_x4t(bh[j2], bb + off);
                    ldsm_x4t(bl[j2], bb + B_BUF + off);
                }
            }
            // term-major: acc RAW distance = 32 HMMAs
#pragma unroll
            for (int i = 0; i < 4; i++)
#pragma unroll
                for (int j = 0; j < 8; j++)
                    mma16816(acc[i][j], ah[i], &bh[j >> 1][(j & 1) * 2]);
#pragma unroll
            for (int i = 0; i < 4; i++)
#pragma unroll
                for (int j = 0; j < 8; j++)
                    mma16816(acc[i][j], ah[i], &bl[j >> 1][(j & 1) * 2]);
#pragma unroll
            for (int i = 0; i < 4; i++)
#pragma unroll
                for (int j = 0; j < 8; j++)
                    mma16816(acc[i][j], al[i], &bh[j >> 1][(j & 1) * 2]);
        }
    }

    // ---- epilogue ----
#pragma unroll
    for (int mi = 0; mi < 4; mi++) {
#pragma unroll
        for (int p = 0; p < 2; p++) {
            int r = m0 + wm + mi * 16 + (lane >> 2) + p * 8;
            size_t rowoff = (size_t)r * N;
#pragma unroll
            for (int nj = 0; nj < 8; nj++) {
                int c = n0 + wn + nj * 8 + (lane & 3) * 2;
                float v0 = acc[mi][nj][p * 2 + 0];
                float v1 = acc[mi][nj][p * 2 + 1];
                if (EPI == 1 || EPI == 3) { v0 += bias[c]; v1 += bias[c + 1]; }
                if (EPI == 3) {
                    float r0 = resid[rowoff + c], r1 = resid[rowoff + c + 1];
                    v0 = r0 + v0 / (1.f + expf(-v0));
                    v1 = r1 + v1 / (1.f + expf(-v1));
                }
                if (EPI == 0 || EPI == 1) {
                    *reinterpret_cast<float2*>(Cf + rowoff + c) = make_float2(v0, v1);
                } else {
                    __nv_bfloat16 h0, l0, h1, l1;
                    split2(v0, h0, l0); split2(v1, h1, l1);
                    *reinterpret_cast<__nv_bfloat162*>(Ch + rowoff + c) = __halves2bfloat162(h0, h1);
                    *reinterpret_cast<__nv_bfloat162*>(Cl + rowoff + c) = __halves2bfloat162(l0, l1);
                }
            }
        }
    }
#undef STAGE
}

#define SMEM_W  (3 * (2 * A_BUF + 2 * 256 * 40 * 2))   // BT stages: 184320
#define SMEM_AC (3 * (2 * A_BUF + 2 * 32 * 264 * 2))   // trans stages: 162816

// ---------------------------------------------------------------------------
// launcher
// ---------------------------------------------------------------------------
extern "C" void kernel_launch(void* const* d_in, const int* in_sizes, int n_in,
                              void* d_out, int out_size)
{
    const float* x    = (const float*)d_in[0];
    const float* W1   = (const float*)d_in[1];
    const float* W2   = (const float*)d_in[2];
    const float* W4   = (const float*)d_in[3];
    const float* b4   = (const float*)d_in[4];
    const float* Wout = (const float*)d_in[5];
    const float* bout = (const float*)d_in[6];
    float* out = (float*)d_out;

    float *xA, *sc;
    __nv_bfloat16 *sx, *w1, *w2, *w4, *wo, *xAT, *xB, *at, *xO, *t;
    cudaGetSymbolAddress((void**)&xA,  g_xA);
    cudaGetSymbolAddress((void**)&sc,  g_sc);
    cudaGetSymbolAddress((void**)&sx,  s_x);
    cudaGetSymbolAddress((void**)&w1,  s_w1);
    cudaGetSymbolAddress((void**)&w2,  s_w2);
    cudaGetSymbolAddress((void**)&w4,  s_w4);
    cudaGetSymbolAddress((void**)&wo,  s_wo);
    cudaGetSymbolAddress((void**)&xAT, s_xAT);
    cudaGetSymbolAddress((void**)&xB,  s_xB);
    cudaGetSymbolAddress((void**)&at,  s_at);
    cudaGetSymbolAddress((void**)&xO,  s_xO);
    cudaGetSymbolAddress((void**)&t,   s_t);

    cudaFuncSetAttribute((const void*)bgemm<0, true>,  cudaFuncAttributeMaxDynamicSharedMemorySize, SMEM_W);
    cudaFuncSetAttribute((const void*)bgemm<1, true>,  cudaFuncAttributeMaxDynamicSharedMemorySize, SMEM_W);
    cudaFuncSetAttribute((const void*)bgemm<2, true>,  cudaFuncAttributeMaxDynamicSharedMemorySize, SMEM_W);
    cudaFuncSetAttribute((const void*)bgemm<3, true>,  cudaFuncAttributeMaxDynamicSharedMemorySize, SMEM_W);
    cudaFuncSetAttribute((const void*)bgemm<0, false>, cudaFuncAttributeMaxDynamicSharedMemorySize, SMEM_AC);
    cudaFuncSetAttribute((const void*)bgemm<2, false>, cudaFuncAttributeMaxDynamicSharedMemorySize, SMEM_AC);

    // splits (weights keep natural [N,K] layout — no transpose!)
    split_rm<<<(unsigned)((PLANE_X / 4 + 255) / 256), 256>>>(x, sx, sx + PLANE_X, PLANE_X / 4);
    split_rm<<<(unsigned)((PLANE_W / 4 + 255) / 256), 256>>>(W1,   w1, w1 + PLANE_W, PLANE_W / 4);
    split_rm<<<(unsigned)((PLANE_W / 4 + 255) / 256), 256>>>(W2,   w2, w2 + PLANE_W, PLANE_W / 4);
    split_rm<<<(unsigned)((PLANE_W / 4 + 255) / 256), 256>>>(W4,   w4, w4 + PLANE_W, PLANE_W / 4);
    split_rm<<<(unsigned)((PLANE_W / 4 + 255) / 256), 256>>>(Wout, wo, wo + PLANE_W, PLANE_W / 4);

    // xA (fp32) and xB (split): M=4096, K=4096, N=4096, B = weights [N,K]
    bgemm<0, true><<<dim3(16, 32, 1), 256, SMEM_W>>>(
        sx, sx + PLANE_X, w1, w1 + PLANE_W, BDIM, BDIM, 0, 0, 0,
        xA, nullptr, nullptr, nullptr, nullptr);
    bgemm<2, true><<<dim3(16, 32, 1), 256, SMEM_W>>>(
        sx, sx + PLANE_X, w2, w2 + PLANE_W, BDIM, BDIM, 0, 0, 0,
        nullptr, xB, xB + PLANE_X, nullptr, nullptr);

    // transpose+split xA per batch: [S,D] -> [D,S]
    split_tr<<<dim3(128, 64, NB), dim3(32, 8, 1)>>>(xA, xAT, xAT + PLANE_AT, SEQ, BDIM);

    // scores[b] = xAT[b] @ xB[b] : M=4096, K=2048, N=4096 (B activations [K,N])
    bgemm<0, false><<<dim3(16, 32, NB), 256, SMEM_AC>>>(
        xAT, xAT + PLANE_AT, xB, xB + PLANE_X,
        SEQ, BDIM,
        (long)BDIM * SEQ, (long)SEQ * BDIM, (long)BDIM * BDIM,
        sc, nullptr, nullptr, nullptr, nullptr);

    // softmax rows -> split attn
    softmax_split<<<NB * BDIM, 256>>>(sc, at, at + PLANE_SC);

    // xO[b] = x[b] @ attn[b] : M=2048, K=4096, N=4096 (B activations)
    bgemm<2, false><<<dim3(16, 16, NB), 256, SMEM_AC>>>(
        sx, sx + PLANE_X, at, at + PLANE_SC,
        BDIM, BDIM,
        (long)SEQ * BDIM, (long)BDIM * BDIM, (long)SEQ * BDIM,
        nullptr, xO, xO + PLANE_X, nullptr, nullptr);

    // t = split(x + silu(xO @ W4^T + b4)) : M=4096, weights
    bgemm<3, true><<<dim3(16, 32, 1), 256, SMEM_W>>>(
        xO, xO + PLANE_X, w4, w4 + PLANE_W,
        BDIM, BDIM, 0, 0, 0,
        nullptr, t, t + PLANE_X, b4, x);

    // out = t @ Wout^T + bout, weights
    bgemm<1, true><<<dim3(16, 32, 1), 256, SMEM_W>>>(
        t, t + PLANE_X, wo, wo + PLANE_W,
        BDIM, BDIM, 0, 0, 0,
        out, nullptr, nullptr, bout, nullptr);
}

// round 6
// speedup vs baseline: 1.1595x; 1.1595x over previous
#include <cuda_runtime.h>
#include <cuda_bf16.h>
#include <math.h>

#define BDIM 4096
#define SEQ  2048
#define NB   2
#define MTOK 4096

typedef unsigned int u32;

// ---------------------------------------------------------------------------
// Static scratch
// ---------------------------------------------------------------------------
__device__ float g_xA[(size_t)NB * SEQ * BDIM];    // fp32 xA (needs transpose)
__device__ float g_sc[(size_t)NB * BDIM * BDIM];   // fp32 scores

static const size_t PLANE_X  = (size_t)MTOK * BDIM;
static const size_t PLANE_W  = (size_t)BDIM * BDIM;
static const size_t PLANE_AT = (size_t)NB * BDIM * SEQ;
static const size_t PLANE_SC = (size_t)NB * BDIM * BDIM;

__device__ __nv_bfloat16 s_x  [2 * PLANE_X];   // x split
__device__ __nv_bfloat16 s_w1 [2 * PLANE_W];   // W1 split (natural [N,K])
__device__ __nv_bfloat16 s_w2 [2 * PLANE_W];
__device__ __nv_bfloat16 s_w4 [2 * PLANE_W];
__device__ __nv_bfloat16 s_wo [2 * PLANE_W];
__device__ __nv_bfloat16 s_xAT[2 * PLANE_AT];  // xA^T split [b][D][S]
__device__ __nv_bfloat16 s_xB [2 * PLANE_X];   // xB split [b][S][D]
__device__ __nv_bfloat16 s_at [2 * PLANE_SC];  // attn split [b][D][D]
__device__ __nv_bfloat16 s_xO [2 * PLANE_X];
__device__ __nv_bfloat16 s_t  [2 * PLANE_X];

// ---------------------------------------------------------------------------
// helpers
// ---------------------------------------------------------------------------
__device__ __forceinline__ void split2(float v, __nv_bfloat16& h, __nv_bfloat16& l) {
    h = __float2bfloat16(v);
    l = __float2bfloat16(v - __bfloat162float(h));
}
__device__ __forceinline__ void cpa16(u32 dst, const void* src) {
    asm volatile("cp.async.cg.shared.global [%0], [%1], 16;\n" :: "r"(dst), "l"(src));
}
__device__ __forceinline__ void cp_commit() { asm volatile("cp.async.commit_group;\n"); }

__device__ __forceinline__ void ldsm_x4(u32* r, u32 addr) {
    asm volatile("ldmatrix.sync.aligned.m8n8.x4.shared.b16 {%0,%1,%2,%3}, [%4];\n"
                 : "=r"(r[0]), "=r"(r[1]), "=r"(r[2]), "=r"(r[3]) : "r"(addr));
}
__device__ __forceinline__ void ldsm_x4t(u32* r, u32 addr) {
    asm volatile("ldmatrix.sync.aligned.m8n8.x4.trans.shared.b16 {%0,%1,%2,%3}, [%4];\n"
                 : "=r"(r[0]), "=r"(r[1]), "=r"(r[2]), "=r"(r[3]) : "r"(addr));
}
__device__ __forceinline__ void mma16816(float* d, const u32* a, const u32* b) {
    asm volatile("mma.sync.aligned.m16n8k16.row.col.f32.bf16.bf16.f32 "
                 "{%0,%1,%2,%3}, {%4,%5,%6,%7}, {%8,%9}, {%0,%1,%2,%3};\n"
                 : "+f"(d[0]), "+f"(d[1]), "+f"(d[2]), "+f"(d[3])
                 : "r"(a[0]), "r"(a[1]), "r"(a[2]), "r"(a[3]), "r"(b[0]), "r"(b[1]));
}

// ---------------------------------------------------------------------------
// split kernels
// ---------------------------------------------------------------------------
__global__ void split_rm(const float* __restrict__ in,
                         __nv_bfloat16* __restrict__ hi,
                         __nv_bfloat16* __restrict__ lo, size_t n4)
{
    size_t i = (size_t)blockIdx.x * blockDim.x + threadIdx.x;
    if (i >= n4) return;
    float4 v = reinterpret_cast<const float4*>(in)[i];
    __nv_bfloat16 h0,l0,h1,l1,h2,l2,h3,l3;
    split2(v.x,h0,l0); split2(v.y,h1,l1); split2(v.z,h2,l2); split2(v.w,h3,l3);
    reinterpret_cast<__nv_bfloat162*>(hi)[2*i+0] = __halves2bfloat162(h0,h1);
    reinterpret_cast<__nv_bfloat162*>(hi)[2*i+1] = __halves2bfloat162(h2,h3);
    reinterpret_cast<__nv_bfloat162*>(lo)[2*i+0] = __halves2bfloat162(l0,l1);
    reinterpret_cast<__nv_bfloat162*>(lo)[2*i+1] = __halves2bfloat162(l2,l3);
}

// in: [R,C] fp32 -> out hi/lo: [C,R] bf16   (batched via blockIdx.z)
__global__ void split_tr(const float* __restrict__ in,
                         __nv_bfloat16* __restrict__ hi,
                         __nv_bfloat16* __restrict__ lo, int R, int C)
{
    __shared__ float tile[32][33];
    size_t boff = (size_t)blockIdx.z * R * C;
    const float* inb = in + boff;
    __nv_bfloat16* hib = hi + boff;
    __nv_bfloat16* lob = lo + boff;
    int c0 = blockIdx.x * 32, r0 = blockIdx.y * 32;
    int tx = threadIdx.x;
#pragma unroll
    for (int i = threadIdx.y; i < 32; i += 8)
        tile[i][tx] = inb[(size_t)(r0 + i) * C + c0 + tx];
    __syncthreads();
#pragma unroll
    for (int i = threadIdx.y; i < 32; i += 8) {
        float v = tile[tx][i];
        __nv_bfloat16 h, l; split2(v, h, l);
        size_t o = (size_t)(c0 + i) * R + r0 + tx;
        hib[o] = h; lob[o] = l;
    }
}

// softmax rows of 4096, fp32 in -> split bf16 out
__global__ __launch_bounds__(256)
void softmax_split(const float* __restrict__ sc,
                   __nv_bfloat16* __restrict__ ah,
                   __nv_bfloat16* __restrict__ al)
{
    __shared__ float sred[32];
    size_t roff = (size_t)blockIdx.x * BDIM;
    const float* p = sc + roff;
    const int tid = threadIdx.x;

    float v[16];
    float m = -3.0e38f;
#pragma unroll
    for (int i = 0; i < 16; i++) { v[i] = p[tid + 256 * i]; m = fmaxf(m, v[i]); }
#pragma unroll
    for (int o = 16; o > 0; o >>= 1) m = fmaxf(m, __shfl_xor_sync(0xffffffffu, m, o));
    if ((tid & 31) == 0) sred[tid >> 5] = m;
    __syncthreads();
    if (tid < 32) {
        float t = (tid < 8) ? sred[tid] : -3.0e38f;
#pragma unroll
        for (int o = 4; o > 0; o >>= 1) t = fmaxf(t, __shfl_xor_sync(0xffffffffu, t, o));
        if (tid == 0) sred[0] = t;
    }
    __syncthreads();
    m = sred[0];

    float s = 0.f;
#pragma unroll
    for (int i = 0; i < 16; i++) { v[i] = expf(v[i] - m); s += v[i]; }
#pragma unroll
    for (int o = 16; o > 0; o >>= 1) s += __shfl_xor_sync(0xffffffffu, s, o);
    __syncthreads();
    if ((tid & 31) == 0) sred[tid >> 5] = s;
    __syncthreads();
    if (tid < 32) {
        float t = (tid < 8) ? sred[tid] : 0.f;
#pragma unroll
        for (int o = 4; o > 0; o >>= 1) t += __shfl_xor_sync(0xffffffffu, t, o);
        if (tid == 0) sred[0] = t;
    }
    __syncthreads();
    float inv = 1.0f / sred[0];
#pragma unroll
    for (int i = 0; i < 16; i++) {
        float w = v[i] * inv;
        __nv_bfloat16 h, l; split2(w, h, l);
        ah[roff + tid + 256 * i] = h;
        al[roff + tid + 256 * i] = l;
    }
}

// ---------------------------------------------------------------------------
// Split-bf16 tensor-core GEMM v4: 2 CTAs/SM.
//   A: [M,K] row-major split.
//   BT=true : B is [N,K] row-major (weights)     -> non-trans ldmatrix
//   BT=false: B is [K,N] row-major (activations) -> trans ldmatrix
//   acc = Ah*Bh + Ah*Bl + Al*Bh (fp32)
// CTA 128x128, warp tile 64x32, 8 warps, BK=32, 2-stage cp.async pipeline.
// EPI: 0 fp32 | 1 fp32+bias | 2 split | 3 split(resid + silu(acc+bias))
// ---------------------------------------------------------------------------
#define A_PITCH 40
#define A_BUF   (128 * A_PITCH * 2)              // 10240 B per plane

template<int EPI, bool BT>
__global__ __launch_bounds__(256, 2)
void bgemm(const __nv_bfloat16* __restrict__ Ah, const __nv_bfloat16* __restrict__ Al,
           const __nv_bfloat16* __restrict__ Bh, const __nv_bfloat16* __restrict__ Bl,
           int K, int N,
           long sA, long sB, long sC,
           float* __restrict__ Cf,
           __nv_bfloat16* __restrict__ Ch, __nv_bfloat16* __restrict__ Cl,
           const float* __restrict__ bias, const float* __restrict__ resid)
{
    constexpr int B_PITCH = BT ? 40 : 136;
    constexpr int B_BUF   = BT ? (128 * 40 * 2) : (32 * 136 * 2);
    constexpr int SOFF_AL = A_BUF;
    constexpr int SOFF_BH = 2 * A_BUF;
    constexpr int SOFF_BL = 2 * A_BUF + B_BUF;
    constexpr int STAGE_BYTES = 2 * A_BUF + 2 * B_BUF;   // 40960 / 37888

    extern __shared__ __align__(16) char smem[];
    const u32 sbase = (u32)__cvta_generic_to_shared(smem);

    const int bz = blockIdx.z;
    Ah += (size_t)bz * sA; Al += (size_t)bz * sA;
    Bh += (size_t)bz * sB; Bl += (size_t)bz * sB;
    if (EPI == 0 || EPI == 1) Cf += (size_t)bz * sC;
    else { Ch += (size_t)bz * sC; Cl += (size_t)bz * sC; }

    // CTA swizzle (GROUP_M = 8)
    const int tiles_n = gridDim.x, tiles_m = gridDim.y;
    int bid = blockIdx.x + blockIdx.y * tiles_n;
    const int G = 8;
    int gsz = G * tiles_n;
    int g   = bid / gsz;
    int rem = bid - g * gsz;
    int gm  = min(G, tiles_m - g * G);
    const int m0 = (g * G + rem % gm) * 128;
    const int n0 = (rem / gm) * 128;

    const int tid  = threadIdx.x;
    const int lane = tid & 31;
    const int wid  = tid >> 5;
    const int wm   = (wid & 1) * 64;
    const int wn   = (wid >> 1) * 32;

    float acc[4][4][4];
#pragma unroll
    for (int i = 0; i < 4; i++)
#pragma unroll
        for (int j = 0; j < 4; j++)
#pragma unroll
            for (int q = 0; q < 4; q++) acc[i][j][q] = 0.f;

    // A staging: 128 rows x 32k per plane = 512 x 16B chunks; 2 per thread
    const int a_row0 = tid >> 2,          a_kc0 = (tid & 3) << 3;
    const int a_row1 = (tid + 256) >> 2,  a_kc1 = ((tid + 256) & 3) << 3;

    const int nk = K >> 5;

#define STAGE(buf, k0) do {                                                          \
    u32 sb_ = sbase + (u32)(buf) * STAGE_BYTES;                                      \
    {                                                                                \
        u32 d0 = sb_ + (u32)(a_row0 * A_PITCH + a_kc0) * 2;                          \
        u32 d1 = sb_ + (u32)(a_row1 * A_PITCH + a_kc1) * 2;                          \
        const __nv_bfloat16* g0 = Ah + (size_t)(m0 + a_row0) * K + (k0) + a_kc0;     \
        const __nv_bfloat16* g1 = Ah + (size_t)(m0 + a_row1) * K + (k0) + a_kc1;     \
        cpa16(d0, g0); cpa16(d1, g1);                                                \
        cpa16(d0 + SOFF_AL, Al + (g0 - Ah));                                         \
        cpa16(d1 + SOFF_AL, Al + (g1 - Ah));                                         \
    }                                                                                \
    if (BT) {                                                                        \
        _Pragma("unroll")                                                            \
        for (int r_ = 0; r_ < 2; r_++) {                                             \
            int c_ = tid + (r_ << 8);                                                \
            int br_ = c_ >> 2, bk_ = (c_ & 3) << 3;                                  \
            u32 d_ = sb_ + SOFF_BH + (u32)(br_ * B_PITCH + bk_) * 2;                 \
            const __nv_bfloat16* gb_ = Bh + (size_t)(n0 + br_) * K + (k0) + bk_;     \
            cpa16(d_, gb_);                                                          \
            cpa16(d_ + B_BUF, Bl + (gb_ - Bh));                                      \
        }                                                                            \
    } else {                                                                         \
        _Pragma("unroll")                                                            \
        for (int r_ = 0; r_ < 2; r_++) {                                             \
            int c_ = tid + (r_ << 8);                                                \
            int br_ = c_ >> 4, bn_ = (c_ & 15) << 3;                                 \
            u32 d_ = sb_ + SOFF_BH + (u32)(br_ * B_PITCH + bn_) * 2;                 \
            const __nv_bfloat16* gb_ = Bh + (size_t)((k0) + br_) * N + n0 + bn_;     \
            cpa16(d_, gb_);                                                          \
            cpa16(d_ + B_BUF, Bl + (gb_ - Bh));                                      \
        }                                                                            \
    }                                                                                \
} while (0)

    STAGE(0, 0);
    cp_commit();

    // ldmatrix lane selectors
    const int aRowSel = lane & 15;
    const int aColSel = (lane >> 4) << 3;
    const int tRowSel = (lane & 7) + (lane & 8);          // B trans
    const int tColSel = (lane & 16) >> 1;
    const int wRowSel = ((lane >> 4) << 3) + (lane & 7);  // B weights
    const int wColSel = lane & 8;

    for (int kt = 0; kt < nk; kt++) {
        if (kt + 1 < nk) {
            STAGE((kt + 1) & 1, (kt + 1) << 5);
            cp_commit();
            asm volatile("cp.async.wait_group 1;");
        } else {
            asm volatile("cp.async.wait_group 0;");
        }
        __syncthreads();

        const u32 ab = sbase + (u32)(kt & 1) * STAGE_BYTES;
        const u32 bb = ab + SOFF_BH;

#pragma unroll
        for (int kk = 0; kk < 32; kk += 16) {
            u32 ah[4][4], al[4][4], bh[2][4], bl[2][4];
#pragma unroll
            for (int i = 0; i < 4; i++) {
                u32 off = (u32)((wm + i * 16 + aRowSel) * A_PITCH + kk + aColSel) * 2;
                ldsm_x4(ah[i], ab + off);
                ldsm_x4(al[i], ab + SOFF_AL + off);
            }
#pragma unroll
            for (int j2 = 0; j2 < 2; j2++) {
                if (BT) {
                    u32 off = (u32)((wn + j2 * 16 + wRowSel) * B_PITCH + kk + wColSel) * 2;
                    ldsm_x4(bh[j2], bb + off);
                    ldsm_x4(bl[j2], bb + B_BUF + off);
                } else {
                    u32 off = (u32)((kk + tRowSel) * B_PITCH + wn + j2 * 16 + tColSel) * 2;
                    ldsm_x4t(bh[j2], bb + off);
                    ldsm_x4t(bl[j2], bb + B_BUF + off);
                }
            }
#pragma unroll
            for (int i = 0; i < 4; i++)
#pragma unroll
                for (int j = 0; j < 4; j++) {
                    const u32* bhp = &bh[j >> 1][(j & 1) * 2];
                    const u32* blp = &bl[j >> 1][(j & 1) * 2];
                    mma16816(acc[i][j], ah[i], bhp);
                    mma16816(acc[i][j], ah[i], blp);
                    mma16816(acc[i][j], al[i], bhp);
                }
        }
        __syncthreads();
    }

    // ---- epilogue ----
#pragma unroll
    for (int mi = 0; mi < 4; mi++) {
#pragma unroll
        for (int p = 0; p < 2; p++) {
            int r = m0 + wm + mi * 16 + (lane >> 2) + p * 8;
            size_t rowoff = (size_t)r * N;
#pragma unroll
            for (int nj = 0; nj < 4; nj++) {
                int c = n0 + wn + nj * 8 + (lane & 3) * 2;
                float v0 = acc[mi][nj][p * 2 + 0];
                float v1 = acc[mi][nj][p * 2 + 1];
                if (EPI == 1 || EPI == 3) { v0 += bias[c]; v1 += bias[c + 1]; }
                if (EPI == 3) {
                    float r0 = resid[rowoff + c], r1 = resid[rowoff + c + 1];
                    v0 = r0 + v0 / (1.f + expf(-v0));
                    v1 = r1 + v1 / (1.f + expf(-v1));
                }
                if (EPI == 0 || EPI == 1) {
                    *reinterpret_cast<float2*>(Cf + rowoff + c) = make_float2(v0, v1);
                } else {
                    __nv_bfloat16 h0, l0, h1, l1;
                    split2(v0, h0, l0); split2(v1, h1, l1);
                    *reinterpret_cast<__nv_bfloat162*>(Ch + rowoff + c) = __halves2bfloat162(h0, h1);
                    *reinterpret_cast<__nv_bfloat162*>(Cl + rowoff + c) = __halves2bfloat162(l0, l1);
                }
            }
        }
    }
#undef STAGE
}

#define SMEM_W  (2 * (2 * A_BUF + 2 * 128 * 40 * 2))   // 81920
#define SMEM_AC (2 * (2 * A_BUF + 2 * 32 * 136 * 2))   // 75776

// ---------------------------------------------------------------------------
// launcher
// ---------------------------------------------------------------------------
extern "C" void kernel_launch(void* const* d_in, const int* in_sizes, int n_in,
                              void* d_out, int out_size)
{
    const float* x    = (const float*)d_in[0];
    const float* W1   = (const float*)d_in[1];
    const float* W2   = (const float*)d_in[2];
    const float* W4   = (const float*)d_in[3];
    const float* b4   = (const float*)d_in[4];
    const float* Wout = (const float*)d_in[5];
    const float* bout = (const float*)d_in[6];
    float* out = (float*)d_out;

    float *xA, *sc;
    __nv_bfloat16 *sx, *w1, *w2, *w4, *wo, *xAT, *xB, *at, *xO, *t;
    cudaGetSymbolAddress((void**)&xA,  g_xA);
    cudaGetSymbolAddress((void**)&sc,  g_sc);
    cudaGetSymbolAddress((void**)&sx,  s_x);
    cudaGetSymbolAddress((void**)&w1,  s_w1);
    cudaGetSymbolAddress((void**)&w2,  s_w2);
    cudaGetSymbolAddress((void**)&w4,  s_w4);
    cudaGetSymbolAddress((void**)&wo,  s_wo);
    cudaGetSymbolAddress((void**)&xAT, s_xAT);
    cudaGetSymbolAddress((void**)&xB,  s_xB);
    cudaGetSymbolAddress((void**)&at,  s_at);
    cudaGetSymbolAddress((void**)&xO,  s_xO);
    cudaGetSymbolAddress((void**)&t,   s_t);

    cudaFuncSetAttribute((const void*)bgemm<0, true>,  cudaFuncAttributeMaxDynamicSharedMemorySize, SMEM_W);
    cudaFuncSetAttribute((const void*)bgemm<1, true>,  cudaFuncAttributeMaxDynamicSharedMemorySize, SMEM_W);
    cudaFuncSetAttribute((const void*)bgemm<2, true>,  cudaFuncAttributeMaxDynamicSharedMemorySize, SMEM_W);
    cudaFuncSetAttribute((const void*)bgemm<3, true>,  cudaFuncAttributeMaxDynamicSharedMemorySize, SMEM_W);
    cudaFuncSetAttribute((const void*)bgemm<0, false>, cudaFuncAttributeMaxDynamicSharedMemorySize, SMEM_AC);
    cudaFuncSetAttribute((const void*)bgemm<2, false>, cudaFuncAttributeMaxDynamicSharedMemorySize, SMEM_AC);

    // splits (weights keep natural [N,K] layout)
    split_rm<<<(unsigned)((PLANE_X / 4 + 255) / 256), 256>>>(x, sx, sx + PLANE_X, PLANE_X / 4);
    split_rm<<<(unsigned)((PLANE_W / 4 + 255) / 256), 256>>>(W1,   w1, w1 + PLANE_W, PLANE_W / 4);
    split_rm<<<(unsigned)((PLANE_W / 4 + 255) / 256), 256>>>(W2,   w2, w2 + PLANE_W, PLANE_W / 4);
    split_rm<<<(unsigned)((PLANE_W / 4 + 255) / 256), 256>>>(W4,   w4, w4 + PLANE_W, PLANE_W / 4);
    split_rm<<<(unsigned)((PLANE_W / 4 + 255) / 256), 256>>>(Wout, wo, wo + PLANE_W, PLANE_W / 4);

    // xA (fp32) and xB (split): M=4096, K=4096, N=4096, B = weights [N,K]
    bgemm<0, true><<<dim3(32, 32, 1), 256, SMEM_W>>>(
        sx, sx + PLANE_X, w1, w1 + PLANE_W, BDIM, BDIM, 0, 0, 0,
        xA, nullptr, nullptr, nullptr, nullptr);
    bgemm<2, true><<<dim3(32, 32, 1), 256, SMEM_W>>>(
        sx, sx + PLANE_X, w2, w2 + PLANE_W, BDIM, BDIM, 0, 0, 0,
        nullptr, xB, xB + PLANE_X, nullptr, nullptr);

    // transpose+split xA per batch: [S,D] -> [D,S]
    split_tr<<<dim3(128, 64, NB), dim3(32, 8, 1)>>>(xA, xAT, xAT + PLANE_AT, SEQ, BDIM);

    // scores[b] = xAT[b] @ xB[b] : M=4096, K=2048, N=4096 (B activations [K,N])
    bgemm<0, false><<<dim3(32, 32, NB), 256, SMEM_AC>>>(
        xAT, xAT + PLANE_AT, xB, xB + PLANE_X,
        SEQ, BDIM,
        (long)BDIM * SEQ, (long)SEQ * BDIM, (long)BDIM * BDIM,
        sc, nullptr, nullptr, nullptr, nullptr);

    // softmax rows -> split attn
    softmax_split<<<NB * BDIM, 256>>>(sc, at, at + PLANE_SC);

    // xO[b] = x[b] @ attn[b] : M=2048, K=4096, N=4096 (B activations)
    bgemm<2, false><<<dim3(32, 16, NB), 256, SMEM_AC>>>(
        sx, sx + PLANE_X, at, at + PLANE_SC,
        BDIM, BDIM,
        (long)SEQ * BDIM, (long)BDIM * BDIM, (long)SEQ * BDIM,
        nullptr, xO, xO + PLANE_X, nullptr, nullptr);

    // t = split(x + silu(xO @ W4^T + b4)) : M=4096, weights
    bgemm<3, true><<<dim3(32, 32, 1), 256, SMEM_W>>>(
        xO, xO + PLANE_X, w4, w4 + PLANE_W,
        BDIM, BDIM, 0, 0, 0,
        nullptr, t, t + PLANE_X, b4, x);

    // out = t @ Wout^T + bout, weights
    bgemm<1, true><<<dim3(32, 32, 1), 256, SMEM_W>>>(
        t, t + PLANE_X, wo, wo + PLANE_W,
        BDIM, BDIM, 0, 0, 0,
        out, nullptr, nullptr, bout, nullptr);
}

// round 7
// speedup vs baseline: 1.1727x; 1.0114x over previous
#include <cuda_runtime.h>
#include <cuda_bf16.h>
#include <math.h>

#define BDIM 4096
#define SEQ  2048
#define NB   2
#define MTOK 4096

typedef unsigned int u32;

// ---------------------------------------------------------------------------
// Static scratch
// ---------------------------------------------------------------------------
__device__ float g_xA[(size_t)NB * SEQ * BDIM];    // fp32 xA (needs transpose)
__device__ float g_sc[(size_t)NB * BDIM * BDIM];   // fp32 scores

static const size_t PLANE_X  = (size_t)MTOK * BDIM;
static const size_t PLANE_W  = (size_t)BDIM * BDIM;
static const size_t PLANE_AT = (size_t)NB * BDIM * SEQ;
static const size_t PLANE_SC = (size_t)NB * BDIM * BDIM;

__device__ __nv_bfloat16 s_x  [2 * PLANE_X];   // x split
__device__ __nv_bfloat16 s_w12[4 * PLANE_W];   // W1 hi,lo then W2 hi,lo ([N,K])
__device__ __nv_bfloat16 s_w4 [2 * PLANE_W];
__device__ __nv_bfloat16 s_wo [2 * PLANE_W];
__device__ __nv_bfloat16 s_xAT[2 * PLANE_AT];  // xA^T split [b][D][S]
__device__ __nv_bfloat16 s_xB [2 * PLANE_X];   // xB split [b][S][D]
__device__ __nv_bfloat16 s_at [2 * PLANE_SC];  // attn split [b][D][D]
__device__ __nv_bfloat16 s_xO [2 * PLANE_X];
__device__ __nv_bfloat16 s_t  [2 * PLANE_X];

// ---------------------------------------------------------------------------
// helpers
// ---------------------------------------------------------------------------
__device__ __forceinline__ void split2(float v, __nv_bfloat16& h, __nv_bfloat16& l) {
    h = __float2bfloat16(v);
    l = __float2bfloat16(v - __bfloat162float(h));
}
__device__ __forceinline__ void cpa16(u32 dst, const void* src) {
    asm volatile("cp.async.cg.shared.global [%0], [%1], 16;\n" :: "r"(dst), "l"(src));
}
__device__ __forceinline__ void cp_commit() { asm volatile("cp.async.commit_group;\n"); }

__device__ __forceinline__ void ldsm_x4(u32* r, u32 addr) {
    asm volatile("ldmatrix.sync.aligned.m8n8.x4.shared.b16 {%0,%1,%2,%3}, [%4];\n"
                 : "=r"(r[0]), "=r"(r[1]), "=r"(r[2]), "=r"(r[3]) : "r"(addr));
}
__device__ __forceinline__ void ldsm_x4t(u32* r, u32 addr) {
    asm volatile("ldmatrix.sync.aligned.m8n8.x4.trans.shared.b16 {%0,%1,%2,%3}, [%4];\n"
                 : "=r"(r[0]), "=r"(r[1]), "=r"(r[2]), "=r"(r[3]) : "r"(addr));
}
__device__ __forceinline__ void mma16816(float* d, const u32* a, const u32* b) {
    asm volatile("mma.sync.aligned.m16n8k16.row.col.f32.bf16.bf16.f32 "
                 "{%0,%1,%2,%3}, {%4,%5,%6,%7}, {%8,%9}, {%0,%1,%2,%3};\n"
                 : "+f"(d[0]), "+f"(d[1]), "+f"(d[2]), "+f"(d[3])
                 : "r"(a[0]), "r"(a[1]), "r"(a[2]), "r"(a[3]), "r"(b[0]), "r"(b[1]));
}

// ---------------------------------------------------------------------------
// split kernels
// ---------------------------------------------------------------------------
__global__ void split_rm(const float* __restrict__ in,
                         __nv_bfloat16* __restrict__ hi,
                         __nv_bfloat16* __restrict__ lo, size_t n4)
{
    size_t i = (size_t)blockIdx.x * blockDim.x + threadIdx.x;
    if (i >= n4) return;
    float4 v = reinterpret_cast<const float4*>(in)[i];
    __nv_bfloat16 h0,l0,h1,l1,h2,l2,h3,l3;
    split2(v.x,h0,l0); split2(v.y,h1,l1); split2(v.z,h2,l2); split2(v.w,h3,l3);
    reinterpret_cast<__nv_bfloat162*>(hi)[2*i+0] = __halves2bfloat162(h0,h1);
    reinterpret_cast<__nv_bfloat162*>(hi)[2*i+1] = __halves2bfloat162(h2,h3);
    reinterpret_cast<__nv_bfloat162*>(lo)[2*i+0] = __halves2bfloat162(l0,l1);
    reinterpret_cast<__nv_bfloat162*>(lo)[2*i+1] = __halves2bfloat162(l2,l3);
}

// batched weight split: z selects which weight
__global__ void split_w4(const float* __restrict__ W1, const float* __restrict__ W2,
                         const float* __restrict__ W4, const float* __restrict__ Wo,
                         __nv_bfloat16* __restrict__ d12,
                         __nv_bfloat16* __restrict__ d4,
                         __nv_bfloat16* __restrict__ dwo, size_t n4)
{
    size_t i = (size_t)blockIdx.x * blockDim.x + threadIdx.x;
    if (i >= n4) return;
    int z = blockIdx.z;
    const float* src = (z == 0) ? W1 : (z == 1) ? W2 : (z == 2) ? W4 : Wo;
    __nv_bfloat16* hi = (z == 0) ? d12 : (z == 1) ? d12 + 2 * PLANE_W
                       : (z == 2) ? d4 : dwo;
    __nv_bfloat16* lo = hi + PLANE_W;
    float4 v = reinterpret_cast<const float4*>(src)[i];
    __nv_bfloat16 h0,l0,h1,l1,h2,l2,h3,l3;
    split2(v.x,h0,l0); split2(v.y,h1,l1); split2(v.z,h2,l2); split2(v.w,h3,l3);
    reinterpret_cast<__nv_bfloat162*>(hi)[2*i+0] = __halves2bfloat162(h0,h1);
    reinterpret_cast<__nv_bfloat162*>(hi)[2*i+1] = __halves2bfloat162(h2,h3);
    reinterpret_cast<__nv_bfloat162*>(lo)[2*i+0] = __halves2bfloat162(l0,l1);
    reinterpret_cast<__nv_bfloat162*>(lo)[2*i+1] = __halves2bfloat162(l2,l3);
}

// in: [R,C] fp32 -> out hi/lo: [C,R] bf16   (batched via blockIdx.z)
__global__ void split_tr(const float* __restrict__ in,
                         __nv_bfloat16* __restrict__ hi,
                         __nv_bfloat16* __restrict__ lo, int R, int C)
{
    __shared__ float tile[32][33];
    size_t boff = (size_t)blockIdx.z * R * C;
    const float* inb = in + boff;
    __nv_bfloat16* hib = hi + boff;
    __nv_bfloat16* lob = lo + boff;
    int c0 = blockIdx.x * 32, r0 = blockIdx.y * 32;
    int tx = threadIdx.x;
#pragma unroll
    for (int i = threadIdx.y; i < 32; i += 8)
        tile[i][tx] = inb[(size_t)(r0 + i) * C + c0 + tx];
    __syncthreads();
#pragma unroll
    for (int i = threadIdx.y; i < 32; i += 8) {
        float v = tile[tx][i];
        __nv_bfloat16 h, l; split2(v, h, l);
        size_t o = (size_t)(c0 + i) * R + r0 + tx;
        hib[o] = h; lob[o] = l;
    }
}

// softmax rows of 4096, fp32 in -> split bf16 out
__global__ __launch_bounds__(256)
void softmax_split(const float* __restrict__ sc,
                   __nv_bfloat16* __restrict__ ah,
                   __nv_bfloat16* __restrict__ al)
{
    __shared__ float sred[32];
    size_t roff = (size_t)blockIdx.x * BDIM;
    const float* p = sc + roff;
    const int tid = threadIdx.x;

    float v[16];
    float m = -3.0e38f;
#pragma unroll
    for (int i = 0; i < 16; i++) { v[i] = p[tid + 256 * i]; m = fmaxf(m, v[i]); }
#pragma unroll
    for (int o = 16; o > 0; o >>= 1) m = fmaxf(m, __shfl_xor_sync(0xffffffffu, m, o));
    if ((tid & 31) == 0) sred[tid >> 5] = m;
    __syncthreads();
    if (tid < 32) {
        float t = (tid < 8) ? sred[tid] : -3.0e38f;
#pragma unroll
        for (int o = 4; o > 0; o >>= 1) t = fmaxf(t, __shfl_xor_sync(0xffffffffu, t, o));
        if (tid == 0) sred[0] = t;
    }
    __syncthreads();
    m = sred[0];

    float s = 0.f;
#pragma unroll
    for (int i = 0; i < 16; i++) { v[i] = expf(v[i] - m); s += v[i]; }
#pragma unroll
    for (int o = 16; o > 0; o >>= 1) s += __shfl_xor_sync(0xffffffffu, s, o);
    __syncthreads();
    if ((tid & 31) == 0) sred[tid >> 5] = s;
    __syncthreads();
    if (tid < 32) {
        float t = (tid < 8) ? sred[tid] : 0.f;
#pragma unroll
        for (int o = 4; o > 0; o >>= 1) t += __shfl_xor_sync(0xffffffffu, t, o);
        if (tid == 0) sred[0] = t;
    }
    __syncthreads();
    float inv = 1.0f / sred[0];
#pragma unroll
    for (int i = 0; i < 16; i++) {
        float w = v[i] * inv;
        __nv_bfloat16 h, l; split2(w, h, l);
        ah[roff + tid + 256 * i] = h;
        al[roff + tid + 256 * i] = l;
    }
}

// ---------------------------------------------------------------------------
// Split-bf16 tensor-core GEMM v5: 2 CTAs/SM, spill-free register schedule.
//   A: [M,K] row-major split.
//   BT=true : B is [N,K] row-major (weights)     -> non-trans ldmatrix
//   BT=false: B is [K,N] row-major (activations) -> trans ldmatrix
//   acc = Ah*Bh + Ah*Bl + Al*Bh (fp32), B fragments blocked by j2-half
// CTA 128x128, warp tile 64x32, 8 warps, BK=32, 2-stage cp.async pipeline.
// EPI: 0 fp32 | 1 fp32+bias | 2 split | 3 split(resid+silu(acc+bias))
//      4 dual (z==0 -> fp32 Cf, z==1 -> split Ch/Cl)  [for merged projections]
// ---------------------------------------------------------------------------
#define A_PITCH 40
#define A_BUF   (128 * A_PITCH * 2)              // 10240 B per plane

template<int EPI, bool BT>
__global__ __launch_bounds__(256, 2)
void bgemm(const __nv_bfloat16* __restrict__ Ah, const __nv_bfloat16* __restrict__ Al,
           const __nv_bfloat16* __restrict__ Bh, const __nv_bfloat16* __restrict__ Bl,
           int K, int N,
           long sA, long sB, long sC,
           float* __restrict__ Cf,
           __nv_bfloat16* __restrict__ Ch, __nv_bfloat16* __restrict__ Cl,
           const float* __restrict__ bias, const float* __restrict__ resid)
{
    constexpr int B_PITCH = BT ? 40 : 136;
    constexpr int B_BUF   = BT ? (128 * 40 * 2) : (32 * 136 * 2);
    constexpr int SOFF_AL = A_BUF;
    constexpr int SOFF_BH = 2 * A_BUF;
    constexpr int SOFF_BL = 2 * A_BUF + B_BUF;
    constexpr int STAGE_BYTES = 2 * A_BUF + 2 * B_BUF;

    extern __shared__ __align__(16) char smem[];
    const u32 sbase = (u32)__cvta_generic_to_shared(smem);

    const int bz = blockIdx.z;
    Ah += (size_t)bz * sA; Al += (size_t)bz * sA;
    Bh += (size_t)bz * sB; Bl += (size_t)bz * sB;
    if (EPI == 0 || EPI == 1) { Cf += (size_t)bz * sC; }
    else if (EPI == 2 || EPI == 3) { Ch += (size_t)bz * sC; Cl += (size_t)bz * sC; }
    // EPI==4: no z offset on outputs (z selects which output is written)

    // CTA swizzle (GROUP_M = 8)
    const int tiles_n = gridDim.x, tiles_m = gridDim.y;
    int bid = blockIdx.x + blockIdx.y * tiles_n;
    const int G = 8;
    int gsz = G * tiles_n;
    int g   = bid / gsz;
    int rem = bid - g * gsz;
    int gm  = min(G, tiles_m - g * G);
    const int m0 = (g * G + rem % gm) * 128;
    const int n0 = (rem / gm) * 128;

    const int tid  = threadIdx.x;
    const int lane = tid & 31;
    const int wid  = tid >> 5;
    const int wm   = (wid & 1) * 64;
    const int wn   = (wid >> 1) * 32;

    float acc[4][4][4];
#pragma unroll
    for (int i = 0; i < 4; i++)
#pragma unroll
        for (int j = 0; j < 4; j++)
#pragma unroll
            for (int q = 0; q < 4; q++) acc[i][j][q] = 0.f;

    // A staging: 128 rows x 32k per plane = 512 x 16B chunks; 2 per thread
    const int a_row0 = tid >> 2,          a_kc0 = (tid & 3) << 3;
    const int a_row1 = (tid + 256) >> 2,  a_kc1 = ((tid + 256) & 3) << 3;

    const int nk = K >> 5;

#define STAGE(buf, k0) do {                                                          \
    u32 sb_ = sbase + (u32)(buf) * STAGE_BYTES;                                      \
    {                                                                                \
        u32 d0 = sb_ + (u32)(a_row0 * A_PITCH + a_kc0) * 2;                          \
        u32 d1 = sb_ + (u32)(a_row1 * A_PITCH + a_kc1) * 2;                          \
        const __nv_bfloat16* g0 = Ah + (size_t)(m0 + a_row0) * K + (k0) + a_kc0;     \
        const __nv_bfloat16* g1 = Ah + (size_t)(m0 + a_row1) * K + (k0) + a_kc1;     \
        cpa16(d0, g0); cpa16(d1, g1);                                                \
        cpa16(d0 + SOFF_AL, Al + (g0 - Ah));                                         \
        cpa16(d1 + SOFF_AL, Al + (g1 - Ah));                                         \
    }                                                                                \
    if (BT) {                                                                        \
        _Pragma("unroll")                                                            \
        for (int r_ = 0; r_ < 2; r_++) {                                             \
            int c_ = tid + (r_ << 8);                                                \
            int br_ = c_ >> 2, bk_ = (c_ & 3) << 3;                                  \
            u32 d_ = sb_ + SOFF_BH + (u32)(br_ * B_PITCH + bk_) * 2;                 \
            const __nv_bfloat16* gb_ = Bh + (size_t)(n0 + br_) * K + (k0) + bk_;     \
            cpa16(d_, gb_);                                                          \
            cpa16(d_ + B_BUF, Bl + (gb_ - Bh));                                      \
        }                                                                            \
    } else {                                                                         \
        _Pragma("unroll")                                                            \
        for (int r_ = 0; r_ < 2; r_++) {                                             \
            int c_ = tid + (r_ << 8);                                                \
            int br_ = c_ >> 4, bn_ = (c_ & 15) << 3;                                 \
            u32 d_ = sb_ + SOFF_BH + (u32)(br_ * B_PITCH + bn_) * 2;                 \
            const __nv_bfloat16* gb_ = Bh + (size_t)((k0) + br_) * N + n0 + bn_;     \
            cpa16(d_, gb_);                                                          \
            cpa16(d_ + B_BUF, Bl + (gb_ - Bh));                                      \
        }                                                                            \
    }                                                                                \
} while (0)

    STAGE(0, 0);
    cp_commit();

    // ldmatrix lane selectors
    const int aRowSel = lane & 15;
    const int aColSel = (lane >> 4) << 3;
    const int tRowSel = (lane & 7) + (lane & 8);          // B trans
    const int tColSel = (lane & 16) >> 1;
    const int wRowSel = ((lane >> 4) << 3) + (lane & 7);  // B weights
    const int wColSel = lane & 8;

    for (int kt = 0; kt < nk; kt++) {
        if (kt + 1 < nk) {
            STAGE((kt + 1) & 1, (kt + 1) << 5);
            cp_commit();
            asm volatile("cp.async.wait_group 1;");
        } else {
            asm volatile("cp.async.wait_group 0;");
        }
        __syncthreads();

        const u32 ab = sbase + (u32)(kt & 1) * STAGE_BYTES;
        const u32 bb = ab + SOFF_BH;

#pragma unroll
        for (int kk = 0; kk < 32; kk += 16) {
            u32 ah[4][4], al[4][4];
#pragma unroll
            for (int i = 0; i < 4; i++) {
                u32 off = (u32)((wm + i * 16 + aRowSel) * A_PITCH + kk + aColSel) * 2;
                ldsm_x4(ah[i], ab + off);
                ldsm_x4(al[i], ab + SOFF_AL + off);
            }
            // B blocked by j2-half: live B regs = 8, total live ~110 (no spills)
#pragma unroll
            for (int j2 = 0; j2 < 2; j2++) {
                u32 bh[4], bl[4];
                if (BT) {
                    u32 off = (u32)((wn + j2 * 16 + wRowSel) * B_PITCH + kk + wColSel) * 2;
                    ldsm_x4(bh, bb + off);
                    ldsm_x4(bl, bb + B_BUF + off);
                } else {
                    u32 off = (u32)((kk + tRowSel) * B_PITCH + wn + j2 * 16 + tColSel) * 2;
                    ldsm_x4t(bh, bb + off);
                    ldsm_x4t(bl, bb + B_BUF + off);
                }
#pragma unroll
                for (int i = 0; i < 4; i++)
#pragma unroll
                    for (int jj = 0; jj < 2; jj++)
                        mma16816(acc[i][j2 * 2 + jj], ah[i], &bh[jj * 2]);
#pragma unroll
                for (int i = 0; i < 4; i++)
#pragma unroll
                    for (int jj = 0; jj < 2; jj++)
                        mma16816(acc[i][j2 * 2 + jj], al[i], &bh[jj * 2]);
#pragma unroll
                for (int i = 0; i < 4; i++)
#pragma unroll
                    for (int jj = 0; jj < 2; jj++)
                        mma16816(acc[i][j2 * 2 + jj], ah[i], &bl[jj * 2]);
            }
        }
        __syncthreads();
    }

    // ---- epilogue ----
    const bool do_f32   = (EPI == 0) || (EPI == 1) || (EPI == 4 && bz == 0);
#pragma unroll
    for (int mi = 0; mi < 4; mi++) {
#pragma unroll
        for (int p = 0; p < 2; p++) {
            int r = m0 + wm + mi * 16 + (lane >> 2) + p * 8;
            size_t rowoff = (size_t)r * N;
#pragma unroll
            for (int nj = 0; nj < 4; nj++) {
                int c = n0 + wn + nj * 8 + (lane & 3) * 2;
                float v0 = acc[mi][nj][p * 2 + 0];
                float v1 = acc[mi][nj][p * 2 + 1];
                if (EPI == 1 || EPI == 3) { v0 += bias[c]; v1 += bias[c + 1]; }
                if (EPI == 3) {
                    float r0 = resid[rowoff + c], r1 = resid[rowoff + c + 1];
                    v0 = r0 + v0 / (1.f + expf(-v0));
                    v1 = r1 + v1 / (1.f + expf(-v1));
                }
                if (do_f32) {
                    *reinterpret_cast<float2*>(Cf + rowoff + c) = make_float2(v0, v1);
                } else {
                    __nv_bfloat16 h0, l0, h1, l1;
                    split2(v0, h0, l0); split2(v1, h1, l1);
                    *reinterpret_cast<__nv_bfloat162*>(Ch + rowoff + c) = __halves2bfloat162(h0, h1);
                    *reinterpret_cast<__nv_bfloat162*>(Cl + rowoff + c) = __halves2bfloat162(l0, l1);
                }
            }
        }
    }
#undef STAGE
}

#define SMEM_W  (2 * (2 * A_BUF + 2 * 128 * 40 * 2))   // 81920
#define SMEM_AC (2 * (2 * A_BUF + 2 * 32 * 136 * 2))   // 75776

// ---------------------------------------------------------------------------
// launcher
// ---------------------------------------------------------------------------
extern "C" void kernel_launch(void* const* d_in, const int* in_sizes, int n_in,
                              void* d_out, int out_size)
{
    const float* x    = (const float*)d_in[0];
    const float* W1   = (const float*)d_in[1];
    const float* W2   = (const float*)d_in[2];
    const float* W4   = (const float*)d_in[3];
    const float* b4   = (const float*)d_in[4];
    const float* Wout = (const float*)d_in[5];
    const float* bout = (const float*)d_in[6];
    float* out = (float*)d_out;

    float *xA, *sc;
    __nv_bfloat16 *sx, *w12, *w4, *wo, *xAT, *xB, *at, *xO, *t;
    cudaGetSymbolAddress((void**)&xA,  g_xA);
    cudaGetSymbolAddress((void**)&sc,  g_sc);
    cudaGetSymbolAddress((void**)&sx,  s_x);
    cudaGetSymbolAddress((void**)&w12, s_w12);
    cudaGetSymbolAddress((void**)&w4,  s_w4);
    cudaGetSymbolAddress((void**)&wo,  s_wo);
    cudaGetSymbolAddress((void**)&xAT, s_xAT);
    cudaGetSymbolAddress((void**)&xB,  s_xB);
    cudaGetSymbolAddress((void**)&at,  s_at);
    cudaGetSymbolAddress((void**)&xO,  s_xO);
    cudaGetSymbolAddress((void**)&t,   s_t);

    cudaFuncSetAttribute((const void*)bgemm<1, true>,  cudaFuncAttributeMaxDynamicSharedMemorySize, SMEM_W);
    cudaFuncSetAttribute((const void*)bgemm<3, true>,  cudaFuncAttributeMaxDynamicSharedMemorySize, SMEM_W);
    cudaFuncSetAttribute((const void*)bgemm<4, true>,  cudaFuncAttributeMaxDynamicSharedMemorySize, SMEM_W);
    cudaFuncSetAttribute((const void*)bgemm<0, false>, cudaFuncAttributeMaxDynamicSharedMemorySize, SMEM_AC);
    cudaFuncSetAttribute((const void*)bgemm<2, false>, cudaFuncAttributeMaxDynamicSharedMemorySize, SMEM_AC);

    // splits: x, then all 4 weights in one batched launch (natural [N,K] layout)
    split_rm<<<(unsigned)((PLANE_X / 4 + 255) / 256), 256>>>(x, sx, sx + PLANE_X, PLANE_X / 4);
    split_w4<<<dim3((unsigned)((PLANE_W / 4 + 255) / 256), 1, 4), 256>>>(
        W1, W2, W4, Wout, w12, w4, wo, PLANE_W / 4);

    // merged projections: z=0 -> xA fp32, z=1 -> xB split (2048 CTAs: ~99% wave)
    bgemm<4, true><<<dim3(32, 32, 2), 256, SMEM_W>>>(
        sx, sx + PLANE_X, w12, w12 + PLANE_W,
        BDIM, BDIM, 0, (long)(2 * PLANE_W), 0,
        xA, xB, xB + PLANE_X, nullptr, nullptr);

    // transpose+split xA per batch: [S,D] -> [D,S]
    split_tr<<<dim3(128, 64, NB), dim3(32, 8, 1)>>>(xA, xAT, xAT + PLANE_AT, SEQ, BDIM);

    // scores[b] = xAT[b] @ xB[b] : M=4096, K=2048, N=4096 (B activations [K,N])
    bgemm<0, false><<<dim3(32, 32, NB), 256, SMEM_AC>>>(
        xAT, xAT + PLANE_AT, xB, xB + PLANE_X,
        SEQ, BDIM,
        (long)BDIM * SEQ, (long)SEQ * BDIM, (long)BDIM * BDIM,
        sc, nullptr, nullptr, nullptr, nullptr);

    // softmax rows -> split attn
    softmax_split<<<NB * BDIM, 256>>>(sc, at, at + PLANE_SC);

    // xO[b] = x[b] @ attn[b] : M=2048, K=4096, N=4096 (B activations)
    bgemm<2, false><<<dim3(32, 16, NB), 256, SMEM_AC>>>(
        sx, sx + PLANE_X, at, at + PLANE_SC,
        BDIM, BDIM,
        (long)SEQ * BDIM, (long)BDIM * BDIM, (long)SEQ * BDIM,
        nullptr, xO, xO + PLANE_X, nullptr, nullptr);

    // t = split(x + silu(xO @ W4^T + b4)) : M=4096, weights
    bgemm<3, true><<<dim3(32, 32, 1), 256, SMEM_W>>>(
        xO, xO + PLANE_X, w4, w4 + PLANE_W,
        BDIM, BDIM, 0, 0, 0,
        nullptr, t, t + PLANE_X, b4, x);

    // out = t @ Wout^T + bout, weights
    bgemm<1, true><<<dim3(32, 32, 1), 256, SMEM_W>>>(
        t, t + PLANE_X, wo, wo + PLANE_W,
        BDIM, BDIM, 0, 0, 0,
        out, nullptr, nullptr, bout, nullptr);
}

// round 8
// speedup vs baseline: 1.2830x; 1.0941x over previous
#include <cuda_runtime.h>
#include <cuda_bf16.h>
#include <math.h>

#define BDIM 4096
#define SEQ  2048
#define NB   2
#define MTOK 4096
#define CAP  512
#define THR  1e-7f

typedef unsigned int u32;

// ---------------------------------------------------------------------------
// Static scratch
// ---------------------------------------------------------------------------
__device__ float g_xA[(size_t)NB * SEQ * BDIM];    // fp32 xA (needs transpose)
__device__ float g_sc[(size_t)NB * BDIM * BDIM];   // fp32 scores

static const size_t PLANE_X  = (size_t)MTOK * BDIM;
static const size_t PLANE_W  = (size_t)BDIM * BDIM;
static const size_t PLANE_AT = (size_t)NB * BDIM * SEQ;

__device__ __nv_bfloat16 s_x  [2 * PLANE_X];   // x split
__device__ __nv_bfloat16 s_w12[4 * PLANE_W];   // W1 hi,lo then W2 hi,lo ([N,K])
__device__ __nv_bfloat16 s_w4 [2 * PLANE_W];
__device__ __nv_bfloat16 s_wo [2 * PLANE_W];
__device__ __nv_bfloat16 s_xAT[2 * PLANE_AT];  // xA^T split [b][D][S]
__device__ __nv_bfloat16 s_xB [2 * PLANE_X];   // xB split [b][S][D]
__device__ __nv_bfloat16 s_xO [2 * PLANE_X];
__device__ __nv_bfloat16 s_t  [2 * PLANE_X];

// sparse-attn compact lists (row = b*BDIM + d)
__device__ unsigned short g_le [(size_t)NB * BDIM * CAP];
__device__ float          g_lw [(size_t)NB * BDIM * CAP];
__device__ int            g_cnt[NB * BDIM];
__device__ float          g_m  [NB * BDIM];
__device__ float          g_iz [NB * BDIM];

// ---------------------------------------------------------------------------
// helpers
// ---------------------------------------------------------------------------
__device__ __forceinline__ void split2(float v, __nv_bfloat16& h, __nv_bfloat16& l) {
    h = __float2bfloat16(v);
    l = __float2bfloat16(v - __bfloat162float(h));
}
__device__ __forceinline__ void cpa16(u32 dst, const void* src) {
    asm volatile("cp.async.cg.shared.global [%0], [%1], 16;\n" :: "r"(dst), "l"(src));
}
__device__ __forceinline__ void cp_commit() { asm volatile("cp.async.commit_group;\n"); }

__device__ __forceinline__ void ldsm_x4(u32* r, u32 addr) {
    asm volatile("ldmatrix.sync.aligned.m8n8.x4.shared.b16 {%0,%1,%2,%3}, [%4];\n"
                 : "=r"(r[0]), "=r"(r[1]), "=r"(r[2]), "=r"(r[3]) : "r"(addr));
}
__device__ __forceinline__ void ldsm_x4t(u32* r, u32 addr) {
    asm volatile("ldmatrix.sync.aligned.m8n8.x4.trans.shared.b16 {%0,%1,%2,%3}, [%4];\n"
                 : "=r"(r[0]), "=r"(r[1]), "=r"(r[2]), "=r"(r[3]) : "r"(addr));
}
__device__ __forceinline__ void mma16816(float* d, const u32* a, const u32* b) {
    asm volatile("mma.sync.aligned.m16n8k16.row.col.f32.bf16.bf16.f32 "
                 "{%0,%1,%2,%3}, {%4,%5,%6,%7}, {%8,%9}, {%0,%1,%2,%3};\n"
                 : "+f"(d[0]), "+f"(d[1]), "+f"(d[2]), "+f"(d[3])
                 : "r"(a[0]), "r"(a[1]), "r"(a[2]), "r"(a[3]), "r"(b[0]), "r"(b[1]));
}

// ---------------------------------------------------------------------------
// split kernels
// ---------------------------------------------------------------------------
__global__ void split_rm(const float* __restrict__ in,
                         __nv_bfloat16* __restrict__ hi,
                         __nv_bfloat16* __restrict__ lo, size_t n4)
{
    size_t i = (size_t)blockIdx.x * blockDim.x + threadIdx.x;
    if (i >= n4) return;
    float4 v = reinterpret_cast<const float4*>(in)[i];
    __nv_bfloat16 h0,l0,h1,l1,h2,l2,h3,l3;
    split2(v.x,h0,l0); split2(v.y,h1,l1); split2(v.z,h2,l2); split2(v.w,h3,l3);
    reinterpret_cast<__nv_bfloat162*>(hi)[2*i+0] = __halves2bfloat162(h0,h1);
    reinterpret_cast<__nv_bfloat162*>(hi)[2*i+1] = __halves2bfloat162(h2,h3);
    reinterpret_cast<__nv_bfloat162*>(lo)[2*i+0] = __halves2bfloat162(l0,l1);
    reinterpret_cast<__nv_bfloat162*>(lo)[2*i+1] = __halves2bfloat162(l2,l3);
}

// batched weight split: z selects which weight
__global__ void split_w4(const float* __restrict__ W1, const float* __restrict__ W2,
                         const float* __restrict__ W4, const float* __restrict__ Wo,
                         __nv_bfloat16* __restrict__ d12,
                         __nv_bfloat16* __restrict__ d4,
                         __nv_bfloat16* __restrict__ dwo, size_t n4)
{
    size_t i = (size_t)blockIdx.x * blockDim.x + threadIdx.x;
    if (i >= n4) return;
    int z = blockIdx.z;
    const float* src = (z == 0) ? W1 : (z == 1) ? W2 : (z == 2) ? W4 : Wo;
    __nv_bfloat16* hi = (z == 0) ? d12 : (z == 1) ? d12 + 2 * PLANE_W
                       : (z == 2) ? d4 : dwo;
    __nv_bfloat16* lo = hi + PLANE_W;
    float4 v = reinterpret_cast<const float4*>(src)[i];
    __nv_bfloat16 h0,l0,h1,l1,h2,l2,h3,l3;
    split2(v.x,h0,l0); split2(v.y,h1,l1); split2(v.z,h2,l2); split2(v.w,h3,l3);
    reinterpret_cast<__nv_bfloat162*>(hi)[2*i+0] = __halves2bfloat162(h0,h1);
    reinterpret_cast<__nv_bfloat162*>(hi)[2*i+1] = __halves2bfloat162(h2,h3);
    reinterpret_cast<__nv_bfloat162*>(lo)[2*i+0] = __halves2bfloat162(l0,l1);
    reinterpret_cast<__nv_bfloat162*>(lo)[2*i+1] = __halves2bfloat162(l2,l3);
}

// in: [R,C] fp32 -> out hi/lo: [C,R] bf16   (batched via blockIdx.z)
__global__ void split_tr(const float* __restrict__ in,
                         __nv_bfloat16* __restrict__ hi,
                         __nv_bfloat16* __restrict__ lo, int R, int C)
{
    __shared__ float tile[32][33];
    size_t boff = (size_t)blockIdx.z * R * C;
    const float* inb = in + boff;
    __nv_bfloat16* hib = hi + boff;
    __nv_bfloat16* lob = lo + boff;
    int c0 = blockIdx.x * 32, r0 = blockIdx.y * 32;
    int tx = threadIdx.x;
#pragma unroll
    for (int i = threadIdx.y; i < 32; i += 8)
        tile[i][tx] = inb[(size_t)(r0 + i) * C + c0 + tx];
    __syncthreads();
#pragma unroll
    for (int i = threadIdx.y; i < 32; i += 8) {
        float v = tile[tx][i];
        __nv_bfloat16 h, l; split2(v, h, l);
        size_t o = (size_t)(c0 + i) * R + r0 + tx;
        hib[o] = h; lob[o] = l;
    }
}

// ---------------------------------------------------------------------------
// softmax rows of 4096 -> compact (e, w) lists with w > THR
// ---------------------------------------------------------------------------
__global__ __launch_bounds__(256)
void softmax_compact(const float* __restrict__ sc,
                     unsigned short* __restrict__ le, float* __restrict__ lw,
                     int* __restrict__ cnt, float* __restrict__ gm,
                     float* __restrict__ giz)
{
    __shared__ float sred[32];
    __shared__ int scnt;
    const int row = blockIdx.x;
    size_t roff = (size_t)row * BDIM;
    const float* p = sc + roff;
    const int tid = threadIdx.x;

    float v[16];
    float m = -3.0e38f;
#pragma unroll
    for (int i = 0; i < 16; i++) { v[i] = p[tid + 256 * i]; m = fmaxf(m, v[i]); }
#pragma unroll
    for (int o = 16; o > 0; o >>= 1) m = fmaxf(m, __shfl_xor_sync(0xffffffffu, m, o));
    if ((tid & 31) == 0) sred[tid >> 5] = m;
    __syncthreads();
    if (tid < 32) {
        float t = (tid < 8) ? sred[tid] : -3.0e38f;
#pragma unroll
        for (int o = 4; o > 0; o >>= 1) t = fmaxf(t, __shfl_xor_sync(0xffffffffu, t, o));
        if (tid == 0) sred[0] = t;
    }
    __syncthreads();
    m = sred[0];

    float s = 0.f;
#pragma unroll
    for (int i = 0; i < 16; i++) { v[i] = expf(v[i] - m); s += v[i]; }
#pragma unroll
    for (int o = 16; o > 0; o >>= 1) s += __shfl_xor_sync(0xffffffffu, s, o);
    __syncthreads();
    if ((tid & 31) == 0) sred[tid >> 5] = s;
    if (tid == 0) scnt = 0;
    __syncthreads();
    if (tid < 32) {
        float t = (tid < 8) ? sred[tid] : 0.f;
#pragma unroll
        for (int o = 4; o > 0; o >>= 1) t += __shfl_xor_sync(0xffffffffu, t, o);
        if (tid == 0) sred[0] = t;
    }
    __syncthreads();
    float inv = 1.0f / sred[0];

    size_t lbase = (size_t)row * CAP;
#pragma unroll
    for (int i = 0; i < 16; i++) {
        float w = v[i] * inv;
        if (w > THR) {
            int slot = atomicAdd(&scnt, 1);
            if (slot < CAP) {
                le[lbase + slot] = (unsigned short)(tid + 256 * i);
                lw[lbase + slot] = w;
            }
        }
    }
    __syncthreads();
    if (tid == 0) { cnt[row] = scnt; gm[row] = m; giz[row] = inv; }
}

// ---------------------------------------------------------------------------
// xO[s,e] = sum_d x[s,d] * attn[d,e], via compact lists. One CTA per (s,b).
// Writes split xO directly. Dense fallback for rows with cnt > CAP.
// ---------------------------------------------------------------------------
__global__ __launch_bounds__(256)
void xo_gather(const float* __restrict__ x, const float* __restrict__ sc,
               const unsigned short* __restrict__ le, const float* __restrict__ lw,
               const int* __restrict__ cnt, const float* __restrict__ gm,
               const float* __restrict__ giz,
               __nv_bfloat16* __restrict__ oh, __nv_bfloat16* __restrict__ ol)
{
    __shared__ float acc[BDIM];
    const int s = blockIdx.x, b = blockIdx.z;
    const int tid = threadIdx.x;
#pragma unroll
    for (int i = tid; i < BDIM; i += 256) acc[i] = 0.f;
    __syncthreads();

    const float* xrow = x + ((size_t)b * SEQ + s) * BDIM;
    const int rbase = b * BDIM;

    for (int d = tid; d < BDIM; d += 256) {
        int row = rbase + d;
        int c = cnt[row];
        float xv = xrow[d];
        if (c <= CAP) {
            size_t lo = (size_t)row * CAP;
            for (int k = 0; k < c; k++) {
                atomicAdd(&acc[le[lo + k]], lw[lo + k] * xv);
            }
        } else {
            // dense fallback (expected never for Gaussian scores)
            float m = gm[row], iz = giz[row];
            const float* srow = sc + (size_t)row * BDIM;
            for (int e = 0; e < BDIM; e++) {
                float w = expf(srow[e] - m) * iz;
                atomicAdd(&acc[e], w * xv);
            }
        }
    }
    __syncthreads();

    size_t obase = ((size_t)b * SEQ + s) * BDIM;
#pragma unroll
    for (int i = tid; i < BDIM; i += 256) {
        __nv_bfloat16 h, l; split2(acc[i], h, l);
        oh[obase + i] = h; ol[obase + i] = l;
    }
}

// ---------------------------------------------------------------------------
// Split-bf16 tensor-core GEMM (R6/R7 proven config): 2 CTAs/SM.
//   A: [M,K] row-major split.
//   BT=true : B is [N,K] row-major (weights)     -> non-trans ldmatrix
//   BT=false: B is [K,N] row-major (activations) -> trans ldmatrix
// CTA 128x128, warp tile 64x32, 8 warps, BK=32, 2-stage cp.async pipeline.
// EPI: 0 fp32 | 1 fp32+bias | 3 split(resid+silu(acc+bias))
//      4 dual (z==0 -> fp32 Cf, z==1 -> split Ch/Cl)
// ---------------------------------------------------------------------------
#define A_PITCH 40
#define A_BUF   (128 * A_PITCH * 2)

template<int EPI, bool BT>
__global__ __launch_bounds__(256, 2)
void bgemm(const __nv_bfloat16* __restrict__ Ah, const __nv_bfloat16* __restrict__ Al,
           const __nv_bfloat16* __restrict__ Bh, const __nv_bfloat16* __restrict__ Bl,
           int K, int N,
           long sA, long sB, long sC,
           float* __restrict__ Cf,
           __nv_bfloat16* __restrict__ Ch, __nv_bfloat16* __restrict__ Cl,
           const float* __restrict__ bias, const float* __restrict__ resid)
{
    constexpr int B_PITCH = BT ? 40 : 136;
    constexpr int B_BUF   = BT ? (128 * 40 * 2) : (32 * 136 * 2);
    constexpr int SOFF_AL = A_BUF;
    constexpr int SOFF_BH = 2 * A_BUF;
    constexpr int SOFF_BL = 2 * A_BUF + B_BUF;
    constexpr int STAGE_BYTES = 2 * A_BUF + 2 * B_BUF;

    extern __shared__ __align__(16) char smem[];
    const u32 sbase = (u32)__cvta_generic_to_shared(smem);

    const int bz = blockIdx.z;
    Ah += (size_t)bz * sA; Al += (size_t)bz * sA;
    Bh += (size_t)bz * sB; Bl += (size_t)bz * sB;
    if (EPI == 0 || EPI == 1) { Cf += (size_t)bz * sC; }
    else if (EPI == 3) { Ch += (size_t)bz * sC; Cl += (size_t)bz * sC; }

    const int tiles_n = gridDim.x, tiles_m = gridDim.y;
    int bid = blockIdx.x + blockIdx.y * tiles_n;
    const int G = 8;
    int gsz = G * tiles_n;
    int g   = bid / gsz;
    int rem = bid - g * gsz;
    int gm  = min(G, tiles_m - g * G);
    const int m0 = (g * G + rem % gm) * 128;
    const int n0 = (rem / gm) * 128;

    const int tid  = threadIdx.x;
    const int lane = tid & 31;
    const int wid  = tid >> 5;
    const int wm   = (wid & 1) * 64;
    const int wn   = (wid >> 1) * 32;

    float acc[4][4][4];
#pragma unroll
    for (int i = 0; i < 4; i++)
#pragma unroll
        for (int j = 0; j < 4; j++)
#pragma unroll
            for (int q = 0; q < 4; q++) acc[i][j][q] = 0.f;

    const int a_row0 = tid >> 2,          a_kc0 = (tid & 3) << 3;
    const int a_row1 = (tid + 256) >> 2,  a_kc1 = ((tid + 256) & 3) << 3;

    const int nk = K >> 5;

#define STAGE(buf, k0) do {                                                          \
    u32 sb_ = sbase + (u32)(buf) * STAGE_BYTES;                                      \
    {                                                                                \
        u32 d0 = sb_ + (u32)(a_row0 * A_PITCH + a_kc0) * 2;                          \
        u32 d1 = sb_ + (u32)(a_row1 * A_PITCH + a_kc1) * 2;                          \
        const __nv_bfloat16* g0 = Ah + (size_t)(m0 + a_row0) * K + (k0) + a_kc0;     \
        const __nv_bfloat16* g1 = Ah + (size_t)(m0 + a_row1) * K + (k0) + a_kc1;     \
        cpa16(d0, g0); cpa16(d1, g1);                                                \
        cpa16(d0 + SOFF_AL, Al + (g0 - Ah));                                         \
        cpa16(d1 + SOFF_AL, Al + (g1 - Ah));                                         \
    }                                                                                \
    if (BT) {                                                                        \
        _Pragma("unroll")                                                            \
        for (int r_ = 0; r_ < 2; r_++) {                                             \
            int c_ = tid + (r_ << 8);                                                \
            int br_ = c_ >> 2, bk_ = (c_ & 3) << 3;                                  \
            u32 d_ = sb_ + SOFF_BH + (u32)(br_ * B_PITCH + bk_) * 2;                 \
            const __nv_bfloat16* gb_ = Bh + (size_t)(n0 + br_) * K + (k0) + bk_;     \
            cpa16(d_, gb_);                                                          \
            cpa16(d_ + B_BUF, Bl + (gb_ - Bh));                                      \
        }                                                                            \
    } else {                                                                         \
        _Pragma("unroll")                                                            \
        for (int r_ = 0; r_ < 2; r_++) {                                             \
            int c_ = tid + (r_ << 8);                                                \
            int br_ = c_ >> 4, bn_ = (c_ & 15) << 3;                                 \
            u32 d_ = sb_ + SOFF_BH + (u32)(br_ * B_PITCH + bn_) * 2;                 \
            const __nv_bfloat16* gb_ = Bh + (size_t)((k0) + br_) * N + n0 + bn_;     \
            cpa16(d_, gb_);                                                          \
            cpa16(d_ + B_BUF, Bl + (gb_ - Bh));                                      \
        }                                                                            \
    }                                                                                \
} while (0)

    STAGE(0, 0);
    cp_commit();

    const int aRowSel = lane & 15;
    const int aColSel = (lane >> 4) << 3;
    const int tRowSel = (lane & 7) + (lane & 8);
    const int tColSel = (lane & 16) >> 1;
    const int wRowSel = ((lane >> 4) << 3) + (lane & 7);
    const int wColSel = lane & 8;

    for (int kt = 0; kt < nk; kt++) {
        if (kt + 1 < nk) {
            STAGE((kt + 1) & 1, (kt + 1) << 5);
            cp_commit();
            asm volatile("cp.async.wait_group 1;");
        } else {
            asm volatile("cp.async.wait_group 0;");
        }
        __syncthreads();

        const u32 ab = sbase + (u32)(kt & 1) * STAGE_BYTES;
        const u32 bb = ab + SOFF_BH;

#pragma unroll
        for (int kk = 0; kk < 32; kk += 16) {
            u32 ah[4][4], al[4][4];
#pragma unroll
            for (int i = 0; i < 4; i++) {
                u32 off = (u32)((wm + i * 16 + aRowSel) * A_PITCH + kk + aColSel) * 2;
                ldsm_x4(ah[i], ab + off);
                ldsm_x4(al[i], ab + SOFF_AL + off);
            }
#pragma unroll
            for (int j2 = 0; j2 < 2; j2++) {
                u32 bh[4], bl[4];
                if (BT) {
                    u32 off = (u32)((wn + j2 * 16 + wRowSel) * B_PITCH + kk + wColSel) * 2;
                    ldsm_x4(bh, bb + off);
                    ldsm_x4(bl, bb + B_BUF + off);
                } else {
                    u32 off = (u32)((kk + tRowSel) * B_PITCH + wn + j2 * 16 + tColSel) * 2;
                    ldsm_x4t(bh, bb + off);
                    ldsm_x4t(bl, bb + B_BUF + off);
                }
#pragma unroll
                for (int i = 0; i < 4; i++)
#pragma unroll
                    for (int jj = 0; jj < 2; jj++)
                        mma16816(acc[i][j2 * 2 + jj], ah[i], &bh[jj * 2]);
#pragma unroll
                for (int i = 0; i < 4; i++)
#pragma unroll
                    for (int jj = 0; jj < 2; jj++)
                        mma16816(acc[i][j2 * 2 + jj], al[i], &bh[jj * 2]);
#pragma unroll
                for (int i = 0; i < 4; i++)
#pragma unroll
                    for (int jj = 0; jj < 2; jj++)
                        mma16816(acc[i][j2 * 2 + jj], ah[i], &bl[jj * 2]);
            }
        }
        __syncthreads();
    }

    const bool do_f32 = (EPI == 0) || (EPI == 1) || (EPI == 4 && bz == 0);
#pragma unroll
    for (int mi = 0; mi < 4; mi++) {
#pragma unroll
        for (int p = 0; p < 2; p++) {
            int r = m0 + wm + mi * 16 + (lane >> 2) + p * 8;
            size_t rowoff = (size_t)r * N;
#pragma unroll
            for (int nj = 0; nj < 4; nj++) {
                int c = n0 + wn + nj * 8 + (lane & 3) * 2;
                float v0 = acc[mi][nj][p * 2 + 0];
                float v1 = acc[mi][nj][p * 2 + 1];
                if (EPI == 1 || EPI == 3) { v0 += bias[c]; v1 += bias[c + 1]; }
                if (EPI == 3) {
                    float r0 = resid[rowoff + c], r1 = resid[rowoff + c + 1];
                    v0 = r0 + v0 / (1.f + expf(-v0));
                    v1 = r1 + v1 / (1.f + expf(-v1));
                }
                if (do_f32) {
                    *reinterpret_cast<float2*>(Cf + rowoff + c) = make_float2(v0, v1);
                } else {
                    __nv_bfloat16 h0, l0, h1, l1;
                    split2(v0, h0, l0); split2(v1, h1, l1);
                    *reinterpret_cast<__nv_bfloat162*>(Ch + rowoff + c) = __halves2bfloat162(h0, h1);
                    *reinterpret_cast<__nv_bfloat162*>(Cl + rowoff + c) = __halves2bfloat162(l0, l1);
                }
            }
        }
    }
#undef STAGE
}

#define SMEM_W  (2 * (2 * A_BUF + 2 * 128 * 40 * 2))   // 81920
#define SMEM_AC (2 * (2 * A_BUF + 2 * 32 * 136 * 2))   // 75776

// ---------------------------------------------------------------------------
// launcher
// ---------------------------------------------------------------------------
extern "C" void kernel_launch(void* const* d_in, const int* in_sizes, int n_in,
                              void* d_out, int out_size)
{
    const float* x    = (const float*)d_in[0];
    const float* W1   = (const float*)d_in[1];
    const float* W2   = (const float*)d_in[2];
    const float* W4   = (const float*)d_in[3];
    const float* b4   = (const float*)d_in[4];
    const float* Wout = (const float*)d_in[5];
    const float* bout = (const float*)d_in[6];
    float* out = (float*)d_out;

    float *xA, *sc, *lw, *gm, *giz;
    int* cnt;
    unsigned short* le;
    __nv_bfloat16 *sx, *w12, *w4, *wo, *xAT, *xB, *xO, *t;
    cudaGetSymbolAddress((void**)&xA,  g_xA);
    cudaGetSymbolAddress((void**)&sc,  g_sc);
    cudaGetSymbolAddress((void**)&sx,  s_x);
    cudaGetSymbolAddress((void**)&w12, s_w12);
    cudaGetSymbolAddress((void**)&w4,  s_w4);
    cudaGetSymbolAddress((void**)&wo,  s_wo);
    cudaGetSymbolAddress((void**)&xAT, s_xAT);
    cudaGetSymbolAddress((void**)&xB,  s_xB);
    cudaGetSymbolAddress((void**)&xO,  s_xO);
    cudaGetSymbolAddress((void**)&t,   s_t);
    cudaGetSymbolAddress((void**)&le,  g_le);
    cudaGetSymbolAddress((void**)&lw,  g_lw);
    cudaGetSymbolAddress((void**)&cnt, g_cnt);
    cudaGetSymbolAddress((void**)&gm,  g_m);
    cudaGetSymbolAddress((void**)&giz, g_iz);

    cudaFuncSetAttribute((const void*)bgemm<1, true>,  cudaFuncAttributeMaxDynamicSharedMemorySize, SMEM_W);
    cudaFuncSetAttribute((const void*)bgemm<3, true>,  cudaFuncAttributeMaxDynamicSharedMemorySize, SMEM_W);
    cudaFuncSetAttribute((const void*)bgemm<4, true>,  cudaFuncAttributeMaxDynamicSharedMemorySize, SMEM_W);
    cudaFuncSetAttribute((const void*)bgemm<0, false>, cudaFuncAttributeMaxDynamicSharedMemorySize, SMEM_AC);

    // splits: x, then all 4 weights in one batched launch (natural [N,K] layout)
    split_rm<<<(unsigned)((PLANE_X / 4 + 255) / 256), 256>>>(x, sx, sx + PLANE_X, PLANE_X / 4);
    split_w4<<<dim3((unsigned)((PLANE_W / 4 + 255) / 256), 1, 4), 256>>>(
        W1, W2, W4, Wout, w12, w4, wo, PLANE_W / 4);

    // merged projections: z=0 -> xA fp32, z=1 -> xB split
    bgemm<4, true><<<dim3(32, 32, 2), 256, SMEM_W>>>(
        sx, sx + PLANE_X, w12, w12 + PLANE_W,
        BDIM, BDIM, 0, (long)(2 * PLANE_W), 0,
        xA, xB, xB + PLANE_X, nullptr, nullptr);

    // transpose+split xA per batch: [S,D] -> [D,S]
    split_tr<<<dim3(128, 64, NB), dim3(32, 8, 1)>>>(xA, xAT, xAT + PLANE_AT, SEQ, BDIM);

    // scores[b] = xAT[b] @ xB[b] : M=4096, K=2048, N=4096 (B activations [K,N])
    bgemm<0, false><<<dim3(32, 32, NB), 256, SMEM_AC>>>(
        xAT, xAT + PLANE_AT, xB, xB + PLANE_X,
        SEQ, BDIM,
        (long)BDIM * SEQ, (long)SEQ * BDIM, (long)BDIM * BDIM,
        sc, nullptr, nullptr, nullptr, nullptr);

    // softmax -> compact sparse lists (threshold THR, cap CAP)
    softmax_compact<<<NB * BDIM, 256>>>(sc, le, lw, cnt, gm, giz);

    // xO = x @ attn via sparse gather, split output directly
    xo_gather<<<dim3(SEQ, 1, NB), 256>>>(x, sc, le, lw, cnt, gm, giz,
                                         xO, xO + PLANE_X);

    // t = split(x + silu(xO @ W4^T + b4)) : M=4096, weights
    bgemm<3, true><<<dim3(32, 32, 1), 256, SMEM_W>>>(
        xO, xO + PLANE_X, w4, w4 + PLANE_W,
        BDIM, BDIM, 0, 0, 0,
        nullptr, t, t + PLANE_X, b4, x);

    // out = t @ Wout^T + bout, weights
    bgemm<1, true><<<dim3(32, 32, 1), 256, SMEM_W>>>(
        t, t + PLANE_X, wo, wo + PLANE_W,
        BDIM, BDIM, 0, 0, 0,
        out, nullptr, nullptr, bout, nullptr);
}

// round 9
// speedup vs baseline: 1.3417x; 1.0457x over previous
#include <cuda_runtime.h>
#include <cuda_bf16.h>
#include <math.h>

#define BDIM 4096
#define SEQ  2048
#define NB   2
#define MTOK 4096
#define CAP  512
#define THR  1e-9f

typedef unsigned int u32;

// ---------------------------------------------------------------------------
// Static scratch
// ---------------------------------------------------------------------------
__device__ float g_xAB[(size_t)2 * NB * SEQ * BDIM]; // fp32 xA then xB
__device__ float g_sc[(size_t)NB * BDIM * BDIM];     // approx (1-term) scores

static const size_t PLANE_X  = (size_t)MTOK * BDIM;
static const size_t PLANE_W  = (size_t)BDIM * BDIM;
static const size_t PLANE_AT = (size_t)NB * BDIM * SEQ;

__device__ __nv_bfloat16 s_x  [2 * PLANE_X];   // x split
__device__ __nv_bfloat16 s_w12[4 * PLANE_W];   // W1 hi,lo then W2 hi,lo ([N,K])
__device__ __nv_bfloat16 s_w4 [2 * PLANE_W];
__device__ __nv_bfloat16 s_wo [2 * PLANE_W];
__device__ __nv_bfloat16 s_xAT[2 * PLANE_AT];  // xA^T split [b][D][S]
__device__ __nv_bfloat16 s_xBT[2 * PLANE_AT];  // xB^T split [b][D][S]
__device__ __nv_bfloat16 s_xO [2 * PLANE_X];
__device__ __nv_bfloat16 s_t  [2 * PLANE_X];

// sparse-attn compact lists (row = b*BDIM + d)
__device__ unsigned short g_le [(size_t)NB * BDIM * CAP];
__device__ float          g_lw [(size_t)NB * BDIM * CAP];
__device__ int            g_cnt[NB * BDIM];
__device__ float          g_m  [NB * BDIM];
__device__ float          g_iz [NB * BDIM];

// ---------------------------------------------------------------------------
// helpers
// ---------------------------------------------------------------------------
__device__ __forceinline__ void split2(float v, __nv_bfloat16& h, __nv_bfloat16& l) {
    h = __float2bfloat16(v);
    l = __float2bfloat16(v - __bfloat162float(h));
}
__device__ __forceinline__ void cpa16(u32 dst, const void* src) {
    asm volatile("cp.async.cg.shared.global [%0], [%1], 16;\n" :: "r"(dst), "l"(src));
}
__device__ __forceinline__ void cp_commit() { asm volatile("cp.async.commit_group;\n"); }

__device__ __forceinline__ void ldsm_x4(u32* r, u32 addr) {
    asm volatile("ldmatrix.sync.aligned.m8n8.x4.shared.b16 {%0,%1,%2,%3}, [%4];\n"
                 : "=r"(r[0]), "=r"(r[1]), "=r"(r[2]), "=r"(r[3]) : "r"(addr));
}
__device__ __forceinline__ void ldsm_x4t(u32* r, u32 addr) {
    asm volatile("ldmatrix.sync.aligned.m8n8.x4.trans.shared.b16 {%0,%1,%2,%3}, [%4];\n"
                 : "=r"(r[0]), "=r"(r[1]), "=r"(r[2]), "=r"(r[3]) : "r"(addr));
}
__device__ __forceinline__ void mma16816(float* d, const u32* a, const u32* b) {
    asm volatile("mma.sync.aligned.m16n8k16.row.col.f32.bf16.bf16.f32 "
                 "{%0,%1,%2,%3}, {%4,%5,%6,%7}, {%8,%9}, {%0,%1,%2,%3};\n"
                 : "+f"(d[0]), "+f"(d[1]), "+f"(d[2]), "+f"(d[3])
                 : "r"(a[0]), "r"(a[1]), "r"(a[2]), "r"(a[3]), "r"(b[0]), "r"(b[1]));
}

// ---------------------------------------------------------------------------
// split kernels
// ---------------------------------------------------------------------------
__global__ void split_rm(const float* __restrict__ in,
                         __nv_bfloat16* __restrict__ hi,
                         __nv_bfloat16* __restrict__ lo, size_t n4)
{
    size_t i = (size_t)blockIdx.x * blockDim.x + threadIdx.x;
    if (i >= n4) return;
    float4 v = reinterpret_cast<const float4*>(in)[i];
    __nv_bfloat16 h0,l0,h1,l1,h2,l2,h3,l3;
    split2(v.x,h0,l0); split2(v.y,h1,l1); split2(v.z,h2,l2); split2(v.w,h3,l3);
    reinterpret_cast<__nv_bfloat162*>(hi)[2*i+0] = __halves2bfloat162(h0,h1);
    reinterpret_cast<__nv_bfloat162*>(hi)[2*i+1] = __halves2bfloat162(h2,h3);
    reinterpret_cast<__nv_bfloat162*>(lo)[2*i+0] = __halves2bfloat162(l0,l1);
    reinterpret_cast<__nv_bfloat162*>(lo)[2*i+1] = __halves2bfloat162(l2,l3);
}

// batched weight split: z selects which weight
__global__ void split_w4(const float* __restrict__ W1, const float* __restrict__ W2,
                         const float* __restrict__ W4, const float* __restrict__ Wo,
                         __nv_bfloat16* __restrict__ d12,
                         __nv_bfloat16* __restrict__ d4,
                         __nv_bfloat16* __restrict__ dwo, size_t n4)
{
    size_t i = (size_t)blockIdx.x * blockDim.x + threadIdx.x;
    if (i >= n4) return;
    int z = blockIdx.z;
    const float* src = (z == 0) ? W1 : (z == 1) ? W2 : (z == 2) ? W4 : Wo;
    __nv_bfloat16* hi = (z == 0) ? d12 : (z == 1) ? d12 + 2 * PLANE_W
                       : (z == 2) ? d4 : dwo;
    __nv_bfloat16* lo = hi + PLANE_W;
    float4 v = reinterpret_cast<const float4*>(src)[i];
    __nv_bfloat16 h0,l0,h1,l1,h2,l2,h3,l3;
    split2(v.x,h0,l0); split2(v.y,h1,l1); split2(v.z,h2,l2); split2(v.w,h3,l3);
    reinterpret_cast<__nv_bfloat162*>(hi)[2*i+0] = __halves2bfloat162(h0,h1);
    reinterpret_cast<__nv_bfloat162*>(hi)[2*i+1] = __halves2bfloat162(h2,h3);
    reinterpret_cast<__nv_bfloat162*>(lo)[2*i+0] = __halves2bfloat162(l0,l1);
    reinterpret_cast<__nv_bfloat162*>(lo)[2*i+1] = __halves2bfloat162(l2,l3);
}

// in: [R,C] fp32 -> out hi/lo: [C,R] bf16   (batched via blockIdx.z)
__global__ void split_tr(const float* __restrict__ in,
                         __nv_bfloat16* __restrict__ hi,
                         __nv_bfloat16* __restrict__ lo, int R, int C)
{
    __shared__ float tile[32][33];
    size_t boff = (size_t)blockIdx.z * R * C;
    const float* inb = in + boff;
    __nv_bfloat16* hib = hi + boff;
    __nv_bfloat16* lob = lo + boff;
    int c0 = blockIdx.x * 32, r0 = blockIdx.y * 32;
    int tx = threadIdx.x;
#pragma unroll
    for (int i = threadIdx.y; i < 32; i += 8)
        tile[i][tx] = inb[(size_t)(r0 + i) * C + c0 + tx];
    __syncthreads();
#pragma unroll
    for (int i = threadIdx.y; i < 32; i += 8) {
        float v = tile[tx][i];
        __nv_bfloat16 h, l; split2(v, h, l);
        size_t o = (size_t)(c0 + i) * R + r0 + tx;
        hib[o] = h; lob[o] = l;
    }
}

// ---------------------------------------------------------------------------
// softmax (on APPROX scores) -> compact candidate lists, wide threshold
// ---------------------------------------------------------------------------
__global__ __launch_bounds__(256)
void softmax_compact(const float* __restrict__ sc,
                     unsigned short* __restrict__ le, float* __restrict__ lw,
                     int* __restrict__ cnt, float* __restrict__ gm,
                     float* __restrict__ giz)
{
    __shared__ float sred[32];
    __shared__ int scnt;
    const int row = blockIdx.x;
    size_t roff = (size_t)row * BDIM;
    const float* p = sc + roff;
    const int tid = threadIdx.x;

    float v[16];
    float m = -3.0e38f;
#pragma unroll
    for (int i = 0; i < 16; i++) { v[i] = p[tid + 256 * i]; m = fmaxf(m, v[i]); }
#pragma unroll
    for (int o = 16; o > 0; o >>= 1) m = fmaxf(m, __shfl_xor_sync(0xffffffffu, m, o));
    if ((tid & 31) == 0) sred[tid >> 5] = m;
    __syncthreads();
    if (tid < 32) {
        float t = (tid < 8) ? sred[tid] : -3.0e38f;
#pragma unroll
        for (int o = 4; o > 0; o >>= 1) t = fmaxf(t, __shfl_xor_sync(0xffffffffu, t, o));
        if (tid == 0) sred[0] = t;
    }
    __syncthreads();
    m = sred[0];

    float s = 0.f;
#pragma unroll
    for (int i = 0; i < 16; i++) { v[i] = expf(v[i] - m); s += v[i]; }
#pragma unroll
    for (int o = 16; o > 0; o >>= 1) s += __shfl_xor_sync(0xffffffffu, s, o);
    __syncthreads();
    if ((tid & 31) == 0) sred[tid >> 5] = s;
    if (tid == 0) scnt = 0;
    __syncthreads();
    if (tid < 32) {
        float t = (tid < 8) ? sred[tid] : 0.f;
#pragma unroll
        for (int o = 4; o > 0; o >>= 1) t += __shfl_xor_sync(0xffffffffu, t, o);
        if (tid == 0) sred[0] = t;
    }
    __syncthreads();
    float inv = 1.0f / sred[0];

    size_t lbase = (size_t)row * CAP;
#pragma unroll
    for (int i = 0; i < 16; i++) {
        float w = v[i] * inv;
        if (w > THR) {
            int slot = atomicAdd(&scnt, 1);
            if (slot < CAP) {
                le[lbase + slot] = (unsigned short)(tid + 256 * i);
                lw[lbase + slot] = w;
            }
        }
    }
    __syncthreads();
    if (tid == 0) { cnt[row] = scnt; gm[row] = m; giz[row] = inv; }
}

// ---------------------------------------------------------------------------
// Recompute EXACT scores for candidate entries from split planes (2^-17 accurate),
// then renormalize softmax over the candidates. Overwrites lw with exact weights.
// ---------------------------------------------------------------------------
__global__ __launch_bounds__(256)
void recompute_exact(const __nv_bfloat16* __restrict__ ath, const __nv_bfloat16* __restrict__ atl,
                     const __nv_bfloat16* __restrict__ bth, const __nv_bfloat16* __restrict__ btl,
                     const unsigned short* __restrict__ le, float* __restrict__ lw,
                     const int* __restrict__ cnt)
{
    __shared__ float a[SEQ];
    __shared__ float red[8];
    const int d = blockIdx.x, b = blockIdx.z;
    const int row = b * BDIM + d;
    int c = cnt[row]; if (c > CAP) c = CAP;
    if (c == 0) return;
    const int tid = threadIdx.x;

    size_t aoff = ((size_t)b * BDIM + d) * SEQ;
    for (int i = tid; i < SEQ; i += 256)
        a[i] = __bfloat162float(ath[aoff + i]) + __bfloat162float(atl[aoff + i]);
    __syncthreads();

    size_t lbase = (size_t)row * CAP;
    for (int k = 0; k < c; k++) {
        int e = le[lbase + k];
        size_t boff = ((size_t)b * BDIM + e) * SEQ;
        float p = 0.f;
        for (int i = tid; i < SEQ; i += 256) {
            float bv = __bfloat162float(bth[boff + i]) + __bfloat162float(btl[boff + i]);
            p += a[i] * bv;
        }
#pragma unroll
        for (int o = 16; o > 0; o >>= 1) p += __shfl_xor_sync(0xffffffffu, p, o);
        if ((tid & 31) == 0) red[tid >> 5] = p;
        __syncthreads();
        if (tid == 0) {
            float s = 0.f;
#pragma unroll
            for (int w = 0; w < 8; w++) s += red[w];
            lw[lbase + k] = s;            // raw exact score (temp)
        }
        __syncthreads();
    }
    if (tid == 0) {
        float m = -3.0e38f;
        for (int k = 0; k < c; k++) m = fmaxf(m, lw[lbase + k]);
        float Z = 0.f;
        for (int k = 0; k < c; k++) Z += expf(lw[lbase + k] - m);
        float iz = 1.0f / Z;
        for (int k = 0; k < c; k++) lw[lbase + k] = expf(lw[lbase + k] - m) * iz;
    }
}

// ---------------------------------------------------------------------------
// xO[s,e] = sum_d x[s,d] * attn[d,e], via compact exact lists. One CTA per (s,b).
// ---------------------------------------------------------------------------
__global__ __launch_bounds__(256)
void xo_gather(const float* __restrict__ x, const float* __restrict__ sc,
               const unsigned short* __restrict__ le, const float* __restrict__ lw,
               const int* __restrict__ cnt, const float* __restrict__ gm,
               const float* __restrict__ giz,
               __nv_bfloat16* __restrict__ oh, __nv_bfloat16* __restrict__ ol)
{
    __shared__ float acc[BDIM];
    const int s = blockIdx.x, b = blockIdx.z;
    const int tid = threadIdx.x;
#pragma unroll
    for (int i = tid; i < BDIM; i += 256) acc[i] = 0.f;
    __syncthreads();

    const float* xrow = x + ((size_t)b * SEQ + s) * BDIM;
    const int rbase = b * BDIM;

    for (int d = tid; d < BDIM; d += 256) {
        int row = rbase + d;
        int c = cnt[row];
        float xv = xrow[d];
        if (c <= CAP) {
            size_t lo = (size_t)row * CAP;
            for (int k = 0; k < c; k++) {
                atomicAdd(&acc[le[lo + k]], lw[lo + k] * xv);
            }
        } else {
            float m = gm[row], iz = giz[row];
            const float* srow = sc + (size_t)row * BDIM;
            for (int e = 0; e < BDIM; e++) {
                float w = expf(srow[e] - m) * iz;
                atomicAdd(&acc[e], w * xv);
            }
        }
    }
    __syncthreads();

    size_t obase = ((size_t)b * SEQ + s) * BDIM;
#pragma unroll
    for (int i = tid; i < BDIM; i += 256) {
        __nv_bfloat16 h, l; split2(acc[i], h, l);
        oh[obase + i] = h; ol[obase + i] = l;
    }
}

// ---------------------------------------------------------------------------
// Split-bf16 tensor-core GEMM: 2 CTAs/SM.
//   A: [M,K] row-major split. B: [N,K] row-major (BT=true, non-trans ldmatrix)
//   TERMS=3: acc = Ah*Bh + Ah*Bl + Al*Bh.  TERMS=1: acc = Ah*Bh only.
// CTA 128x128, warp tile 64x32, 8 warps, BK=32, 2-stage cp.async pipeline.
// EPI: 0 fp32 | 1 fp32+bias | 3 split(resid+silu(acc+bias))
// ---------------------------------------------------------------------------
#define A_PITCH 40
#define A_BUF   (128 * A_PITCH * 2)

template<int EPI, bool BT, int TERMS>
__global__ __launch_bounds__(256, 2)
void bgemm(const __nv_bfloat16* __restrict__ Ah, const __nv_bfloat16* __restrict__ Al,
           const __nv_bfloat16* __restrict__ Bh, const __nv_bfloat16* __restrict__ Bl,
           int K, int N,
           long sA, long sB, long sC,
           float* __restrict__ Cf,
           __nv_bfloat16* __restrict__ Ch, __nv_bfloat16* __restrict__ Cl,
           const float* __restrict__ bias, const float* __restrict__ resid)
{
    constexpr int B_PITCH = BT ? 40 : 136;
    constexpr int B_BUF   = BT ? (128 * 40 * 2) : (32 * 136 * 2);
    constexpr int NPL     = (TERMS == 3) ? 2 : 1;
    constexpr int SOFF_AL = A_BUF;
    constexpr int SOFF_BH = NPL * A_BUF;
    constexpr int SOFF_BL = NPL * A_BUF + B_BUF;
    constexpr int STAGE_BYTES = NPL * A_BUF + NPL * B_BUF;

    extern __shared__ __align__(16) char smem[];
    const u32 sbase = (u32)__cvta_generic_to_shared(smem);

    const int bz = blockIdx.z;
    Ah += (size_t)bz * sA; Al += (size_t)bz * sA;
    Bh += (size_t)bz * sB; Bl += (size_t)bz * sB;
    if (EPI == 0 || EPI == 1) { Cf += (size_t)bz * sC; }
    else { Ch += (size_t)bz * sC; Cl += (size_t)bz * sC; }

    const int tiles_n = gridDim.x, tiles_m = gridDim.y;
    int bid = blockIdx.x + blockIdx.y * tiles_n;
    const int G = 8;
    int gsz = G * tiles_n;
    int g   = bid / gsz;
    int rem = bid - g * gsz;
    int gm  = min(G, tiles_m - g * G);
    const int m0 = (g * G + rem % gm) * 128;
    const int n0 = (rem / gm) * 128;

    const int tid  = threadIdx.x;
    const int lane = tid & 31;
    const int wid  = tid >> 5;
    const int wm   = (wid & 1) * 64;
    const int wn   = (wid >> 1) * 32;

    float acc[4][4][4];
#pragma unroll
    for (int i = 0; i < 4; i++)
#pragma unroll
        for (int j = 0; j < 4; j++)
#pragma unroll
            for (int q = 0; q < 4; q++) acc[i][j][q] = 0.f;

    const int a_row0 = tid >> 2,          a_kc0 = (tid & 3) << 3;
    const int a_row1 = (tid + 256) >> 2,  a_kc1 = ((tid + 256) & 3) << 3;

    const int nk = K >> 5;

#define STAGE(buf, k0) do {                                                          \
    u32 sb_ = sbase + (u32)(buf) * STAGE_BYTES;                                      \
    {                                                                                \
        u32 d0 = sb_ + (u32)(a_row0 * A_PITCH + a_kc0) * 2;                          \
        u32 d1 = sb_ + (u32)(a_row1 * A_PITCH + a_kc1) * 2;                          \
        const __nv_bfloat16* g0 = Ah + (size_t)(m0 + a_row0) * K + (k0) + a_kc0;     \
        const __nv_bfloat16* g1 = Ah + (size_t)(m0 + a_row1) * K + (k0) + a_kc1;     \
        cpa16(d0, g0); cpa16(d1, g1);                                                \
        if (TERMS == 3) {                                                            \
            cpa16(d0 + SOFF_AL, Al + (g0 - Ah));                                     \
            cpa16(d1 + SOFF_AL, Al + (g1 - Ah));                                     \
        }                                                                            \
    }                                                                                \
    if (BT) {                                                                        \
        _Pragma("unroll")                                                            \
        for (int r_ = 0; r_ < 2; r_++) {                                             \
            int c_ = tid + (r_ << 8);                                                \
            int br_ = c_ >> 2, bk_ = (c_ & 3) << 3;                                  \
            u32 d_ = sb_ + SOFF_BH + (u32)(br_ * B_PITCH + bk_) * 2;                 \
            const __nv_bfloat16* gb_ = Bh + (size_t)(n0 + br_) * K + (k0) + bk_;     \
            cpa16(d_, gb_);                                                          \
            if (TERMS == 3) cpa16(d_ + B_BUF, Bl + (gb_ - Bh));                      \
        }                                                                            \
    } else {                                                                         \
        _Pragma("unroll")                                                            \
        for (int r_ = 0; r_ < 2; r_++) {                                             \
            int c_ = tid + (r_ << 8);                                                \
            int br_ = c_ >> 4, bn_ = (c_ & 15) << 3;                                 \
            u32 d_ = sb_ + SOFF_BH + (u32)(br_ * B_PITCH + bn_) * 2;                 \
            const __nv_bfloat16* gb_ = Bh + (size_t)((k0) + br_) * N + n0 + bn_;     \
            cpa16(d_, gb_);                                                          \
            if (TERMS == 3) cpa16(d_ + B_BUF, Bl + (gb_ - Bh));                      \
        }                                                                            \
    }                                                                                \
} while (0)

    STAGE(0, 0);
    cp_commit();

    const int aRowSel = lane & 15;
    const int aColSel = (lane >> 4) << 3;
    const int tRowSel = (lane & 7) + (lane & 8);
    const int tColSel = (lane & 16) >> 1;
    const int wRowSel = ((lane >> 4) << 3) + (lane & 7);
    const int wColSel = lane & 8;

    for (int kt = 0; kt < nk; kt++) {
        if (kt + 1 < nk) {
            STAGE((kt + 1) & 1, (kt + 1) << 5);
            cp_commit();
            asm volatile("cp.async.wait_group 1;");
        } else {
            asm volatile("cp.async.wait_group 0;");
        }
        __syncthreads();

        const u32 ab = sbase + (u32)(kt & 1) * STAGE_BYTES;
        const u32 bb = ab + SOFF_BH;

#pragma unroll
        for (int kk = 0; kk < 32; kk += 16) {
            u32 ah[4][4], al[4][4];
#pragma unroll
            for (int i = 0; i < 4; i++) {
                u32 off = (u32)((wm + i * 16 + aRowSel) * A_PITCH + kk + aColSel) * 2;
                ldsm_x4(ah[i], ab + off);
                if (TERMS == 3) ldsm_x4(al[i], ab + SOFF_AL + off);
            }
#pragma unroll
            for (int j2 = 0; j2 < 2; j2++) {
                u32 bh[4], bl[4];
                if (BT) {
                    u32 off = (u32)((wn + j2 * 16 + wRowSel) * B_PITCH + kk + wColSel) * 2;
                    ldsm_x4(bh, bb + off);
                    if (TERMS == 3) ldsm_x4(bl, bb + B_BUF + off);
                } else {
                    u32 off = (u32)((kk + tRowSel) * B_PITCH + wn + j2 * 16 + tColSel) * 2;
                    ldsm_x4t(bh, bb + off);
                    if (TERMS == 3) ldsm_x4t(bl, bb + B_BUF + off);
                }
#pragma unroll
                for (int i = 0; i < 4; i++)
#pragma unroll
                    for (int jj = 0; jj < 2; jj++)
                        mma16816(acc[i][j2 * 2 + jj], ah[i], &bh[jj * 2]);
                if (TERMS == 3) {
#pragma unroll
                    for (int i = 0; i < 4; i++)
#pragma unroll
                        for (int jj = 0; jj < 2; jj++)
                            mma16816(acc[i][j2 * 2 + jj], al[i], &bh[jj * 2]);
#pragma unroll
                    for (int i = 0; i < 4; i++)
#pragma unroll
                        for (int jj = 0; jj < 2; jj++)
                            mma16816(acc[i][j2 * 2 + jj], ah[i], &bl[jj * 2]);
                }
            }
        }
        __syncthreads();
    }

    const bool do_f32 = (EPI == 0) || (EPI == 1);
#pragma unroll
    for (int mi = 0; mi < 4; mi++) {
#pragma unroll
        for (int p = 0; p < 2; p++) {
            int r = m0 + wm + mi * 16 + (lane >> 2) + p * 8;
            size_t rowoff = (size_t)r * N;
#pragma unroll
            for (int nj = 0; nj < 4; nj++) {
                int c = n0 + wn + nj * 8 + (lane & 3) * 2;
                float v0 = acc[mi][nj][p * 2 + 0];
                float v1 = acc[mi][nj][p * 2 + 1];
                if (EPI == 1 || EPI == 3) { v0 += bias[c]; v1 += bias[c + 1]; }
                if (EPI == 3) {
                    float r0 = resid[rowoff + c], r1 = resid[rowoff + c + 1];
                    v0 = r0 + v0 / (1.f + expf(-v0));
                    v1 = r1 + v1 / (1.f + expf(-v1));
                }
                if (do_f32) {
                    *reinterpret_cast<float2*>(Cf + rowoff + c) = make_float2(v0, v1);
                } else {
                    __nv_bfloat16 h0, l0, h1, l1;
                    split2(v0, h0, l0); split2(v1, h1, l1);
                    *reinterpret_cast<__nv_bfloat162*>(Ch + rowoff + c) = __halves2bfloat162(h0, h1);
                    *reinterpret_cast<__nv_bfloat162*>(Cl + rowoff + c) = __halves2bfloat162(l0, l1);
                }
            }
        }
    }
#undef STAGE
}

#define SMEM_W  (2 * (2 * A_BUF + 2 * 128 * 40 * 2))   // 81920 (TERMS=3, BT)
#define SMEM_S  (2 * (A_BUF + 128 * 40 * 2))           // 40960 (TERMS=1, BT)

// ---------------------------------------------------------------------------
// launcher
// ---------------------------------------------------------------------------
extern "C" void kernel_launch(void* const* d_in, const int* in_sizes, int n_in,
                              void* d_out, int out_size)
{
    const float* x    = (const float*)d_in[0];
    const float* W1   = (const float*)d_in[1];
    const float* W2   = (const float*)d_in[2];
    const float* W4   = (const float*)d_in[3];
    const float* b4   = (const float*)d_in[4];
    const float* Wout = (const float*)d_in[5];
    const float* bout = (const float*)d_in[6];
    float* out = (float*)d_out;

    float *xAB, *sc, *lw, *gm, *giz;
    int* cnt;
    unsigned short* le;
    __nv_bfloat16 *sx, *w12, *w4, *wo, *xAT, *xBT, *xO, *t;
    cudaGetSymbolAddress((void**)&xAB, g_xAB);
    cudaGetSymbolAddress((void**)&sc,  g_sc);
    cudaGetSymbolAddress((void**)&sx,  s_x);
    cudaGetSymbolAddress((void**)&w12, s_w12);
    cudaGetSymbolAddress((void**)&w4,  s_w4);
    cudaGetSymbolAddress((void**)&wo,  s_wo);
    cudaGetSymbolAddress((void**)&xAT, s_xAT);
    cudaGetSymbolAddress((void**)&xBT, s_xBT);
    cudaGetSymbolAddress((void**)&xO,  s_xO);
    cudaGetSymbolAddress((void**)&t,   s_t);
    cudaGetSymbolAddress((void**)&le,  g_le);
    cudaGetSymbolAddress((void**)&lw,  g_lw);
    cudaGetSymbolAddress((void**)&cnt, g_cnt);
    cudaGetSymbolAddress((void**)&gm,  g_m);
    cudaGetSymbolAddress((void**)&giz, g_iz);

    cudaFuncSetAttribute((const void*)bgemm<0, true, 3>, cudaFuncAttributeMaxDynamicSharedMemorySize, SMEM_W);
    cudaFuncSetAttribute((const void*)bgemm<1, true, 3>, cudaFuncAttributeMaxDynamicSharedMemorySize, SMEM_W);
    cudaFuncSetAttribute((const void*)bgemm<3, true, 3>, cudaFuncAttributeMaxDynamicSharedMemorySize, SMEM_W);
    cudaFuncSetAttribute((const void*)bgemm<0, true, 1>, cudaFuncAttributeMaxDynamicSharedMemorySize, SMEM_S);

    // splits: x, then all 4 weights in one batched launch (natural [N,K] layout)
    split_rm<<<(unsigned)((PLANE_X / 4 + 255) / 256), 256>>>(x, sx, sx + PLANE_X, PLANE_X / 4);
    split_w4<<<dim3((unsigned)((PLANE_W / 4 + 255) / 256), 1, 4), 256>>>(
        W1, W2, W4, Wout, w12, w4, wo, PLANE_W / 4);

    // merged projections: z=0 -> xA fp32, z=1 -> xB fp32 (3-term exact)
    bgemm<0, true, 3><<<dim3(32, 32, 2), 256, SMEM_W>>>(
        sx, sx + PLANE_X, w12, w12 + PLANE_W,
        BDIM, BDIM, 0, (long)(2 * PLANE_W), (long)PLANE_X,
        xAB, nullptr, nullptr, nullptr, nullptr);

    // transpose+split per batch: [S,D] -> [D,S]
    split_tr<<<dim3(128, 64, NB), dim3(32, 8, 1)>>>(xAB,           xAT, xAT + PLANE_AT, SEQ, BDIM);
    split_tr<<<dim3(128, 64, NB), dim3(32, 8, 1)>>>(xAB + PLANE_X, xBT, xBT + PLANE_AT, SEQ, BDIM);

    // APPROX scores[b] = xAT[b] @ xBT[b]^T : 1-term bf16 (selection only)
    bgemm<0, true, 1><<<dim3(32, 32, NB), 256, SMEM_S>>>(
        xAT, xAT, xBT, xBT,
        SEQ, BDIM,
        (long)BDIM * SEQ, (long)BDIM * SEQ, (long)BDIM * BDIM,
        sc, nullptr, nullptr, nullptr, nullptr);

    // candidate selection (wide threshold on approx weights)
    softmax_compact<<<NB * BDIM, 256>>>(sc, le, lw, cnt, gm, giz);

    // exact score recompute + renormalize over candidates
    recompute_exact<<<dim3(BDIM, 1, NB), 256>>>(
        xAT, xAT + PLANE_AT, xBT, xBT + PLANE_AT, le, lw, cnt);

    // xO = x @ attn via sparse gather (exact weights), split output
    xo_gather<<<dim3(SEQ, 1, NB), 256>>>(x, sc, le, lw, cnt, gm, giz,
                                         xO, xO + PLANE_X);

    // t = split(x + silu(xO @ W4^T + b4)) : M=4096, weights
    bgemm<3, true, 3><<<dim3(32, 32, 1), 256, SMEM_W>>>(
        xO, xO + PLANE_X, w4, w4 + PLANE_W,
        BDIM, BDIM, 0, 0, 0,
        nullptr, t, t + PLANE_X, b4, x);

    // out = t @ Wout^T + bout, weights
    bgemm<1, true, 3><<<dim3(32, 32, 1), 256, SMEM_W>>>(
        t, t + PLANE_X, wo, wo + PLANE_W,
        BDIM, BDIM, 0, 0, 0,
        out, nullptr, nullptr, bout, nullptr);
}